// round 8
// baseline (speedup 1.0000x reference)
#include <cuda_runtime.h>
#include <cuda_bf16.h>
#include <cstdint>

#define B_  2
#define T_  2048
#define C_  1024
#define H_  16
#define DH  64
#define M_  (B_ * T_)
#define KD  1024

// ---------------- scratch (static device globals) ----------------
__device__ __nv_bfloat16 g_xhi[(size_t)M_ * KD];
__device__ __nv_bfloat16 g_xlo[(size_t)M_ * KD];
__device__ __nv_bfloat16 g_wahi[(size_t)3 * C_ * KD];   // W_attn^T [3072,1024]
__device__ __nv_bfloat16 g_walo[(size_t)3 * C_ * KD];
__device__ __nv_bfloat16 g_wphi[(size_t)C_ * KD];       // W_proj^T [1024,1024]
__device__ __nv_bfloat16 g_wplo[(size_t)C_ * KD];
__device__ __nv_bfloat16 g_yhi[(size_t)M_ * KD];        // attention out (hi)
__device__ __nv_bfloat16 g_ylo[(size_t)M_ * KD];        // attention out (lo)
// head-major attention operands (written by fused QKV epilogue)
__device__ __nv_bfloat16 g_qh[(size_t)B_ * H_ * T_ * DH];
__device__ __nv_bfloat16 g_ql[(size_t)B_ * H_ * T_ * DH];
__device__ __nv_bfloat16 g_kh[(size_t)B_ * H_ * T_ * DH];
__device__ __nv_bfloat16 g_kl[(size_t)B_ * H_ * T_ * DH];
__device__ __nv_bfloat16 g_vth[(size_t)B_ * H_ * DH * T_];   // transposed [bh][d][t]
__device__ __nv_bfloat16 g_vtl[(size_t)B_ * H_ * DH * T_];

// ---------------- base-ISA PTX helpers (sm_80+) ----------------
__device__ __forceinline__ uint32_t smem_u32(const void* p) {
    uint32_t a;
    asm("{ .reg .u64 t; cvta.to.shared.u64 t, %1; cvt.u32.u64 %0, t; }" : "=r"(a) : "l"(p));
    return a;
}
__device__ __forceinline__ void cp16(uint32_t s, const void* g) {
    asm volatile("cp.async.cg.shared.global [%0], [%1], 16;" :: "r"(s), "l"(g));
}
__device__ __forceinline__ void cp_commit() {
    asm volatile("cp.async.commit_group;" ::: "memory");
}
__device__ __forceinline__ void cp_wait1() {
    asm volatile("cp.async.wait_group 1;" ::: "memory");
}
__device__ __forceinline__ void cp_wait0() {
    asm volatile("cp.async.wait_group 0;" ::: "memory");
}
#define LDSM4(R, addr) \
    asm volatile("ldmatrix.sync.aligned.m8n8.x4.shared.b16 {%0,%1,%2,%3}, [%4];" \
                 : "=r"((R)[0]), "=r"((R)[1]), "=r"((R)[2]), "=r"((R)[3]) : "r"(addr))

__device__ __forceinline__ void mma16816(float* c, const uint32_t* a, const uint32_t* b) {
    asm volatile(
        "mma.sync.aligned.m16n8k16.row.col.f32.bf16.bf16.f32 "
        "{%0,%1,%2,%3}, {%4,%5,%6,%7}, {%8,%9}, {%0,%1,%2,%3};"
        : "+f"(c[0]), "+f"(c[1]), "+f"(c[2]), "+f"(c[3])
        : "r"(a[0]), "r"(a[1]), "r"(a[2]), "r"(a[3]), "r"(b[0]), "r"(b[1]));
}
__device__ __forceinline__ uint32_t pack_bf16x2(float lo, float hi) {
    uint32_t d;
    asm("cvt.rn.bf16x2.f32 %0, %1, %2;" : "=r"(d) : "f"(hi), "f"(lo));
    return d;
}

// ---------------- fp32 -> bf16 hi/lo split ----------------
__device__ __forceinline__ void split2(float v, __nv_bfloat16& h, __nv_bfloat16& l) {
    h = __float2bfloat16(v);
    l = __float2bfloat16(v - __bfloat162float(h));
}

__global__ __launch_bounds__(256)
void split_kernel(const float* __restrict__ in,
                  __nv_bfloat16* __restrict__ hi, __nv_bfloat16* __restrict__ lo, int n)
{
    int i = (blockIdx.x * 256 + threadIdx.x) * 4;
    if (i >= n) return;
    float4 v = *(const float4*)(in + i);
    __nv_bfloat16 h0, h1, h2, h3, l0, l1, l2, l3;
    split2(v.x, h0, l0); split2(v.y, h1, l1);
    split2(v.z, h2, l2); split2(v.w, h3, l3);
    *(__nv_bfloat162*)(hi + i)     = __halves2bfloat162(h0, h1);
    *(__nv_bfloat162*)(hi + i + 2) = __halves2bfloat162(h2, h3);
    *(__nv_bfloat162*)(lo + i)     = __halves2bfloat162(l0, l1);
    *(__nv_bfloat162*)(lo + i + 2) = __halves2bfloat162(l2, l3);
}

__global__ __launch_bounds__(256)
void splitT_kernel(const float* __restrict__ W,
                   __nv_bfloat16* __restrict__ hiT, __nv_bfloat16* __restrict__ loT,
                   int Kdim, int Ndim)
{
    __shared__ float tile[32][33];
    const int k0 = blockIdx.x * 32, n0 = blockIdx.y * 32;
    const int tx = threadIdx.x, ty = threadIdx.y;   // 32 x 8
    #pragma unroll
    for (int i = 0; i < 32; i += 8)
        tile[ty + i][tx] = W[(size_t)(k0 + ty + i) * Ndim + n0 + tx];
    __syncthreads();
    #pragma unroll
    for (int i = 0; i < 32; i += 8) {
        float v = tile[tx][ty + i];
        __nv_bfloat16 h, l;
        split2(v, h, l);
        size_t o = (size_t)(n0 + ty + i) * Kdim + k0 + tx;
        hiT[o] = h;
        loT[o] = l;
    }
}

// ---------------------------------------------------------------------------
// bf16x3 HMMA GEMM mainloop (round-4 measured-best config):
// CTA 128x128, 8 warps 2(M) x 4(N), warp tile 64x32, BK=64,
// 2-stage cp.async pipeline, compute -> sync -> load -> wait -> sync.
// ---------------------------------------------------------------------------
#define MAT_BYTES   16384
#define STAGE_BYTES (4 * MAT_BYTES)
#define GEMM_SMEM   (2 * STAGE_BYTES)
#define NSTAGE      (KD / 64)

__device__ __forceinline__ void gemm_mainloop(
    const __nv_bfloat16* __restrict__ Ahi, const __nv_bfloat16* __restrict__ Alo,
    const __nv_bfloat16* __restrict__ Bhi, const __nv_bfloat16* __restrict__ Blo,
    int m0, int n0, uint32_t smem, float (&acc)[4][4][4])
{
    const int tid    = threadIdx.x;
    const int lane   = tid & 31;
    const int warp   = tid >> 5;
    const int warp_m = warp & 1;
    const int warp_n = warp >> 1;

    const __nv_bfloat16* mats[4] = { Ahi, Alo, Bhi, Blo };
    const int rowbase[2] = { m0, n0 };

    auto load_stage = [&](int kofs, uint32_t stage_u32) {
        #pragma unroll
        for (int t = 0; t < 16; t++) {
            const int mat = t >> 2;
            const int rem = ((t & 3) << 8) + tid;
            const int row = rem >> 3;
            const int ch  = tid & 7;
            const __nv_bfloat16* g = mats[mat]
                + (size_t)(rowbase[mat >> 1] + row) * KD + kofs + ch * 8;
            uint32_t s = stage_u32 + mat * MAT_BYTES + row * 128
                       + ((ch ^ (row & 7)) << 4);
            cp16(s, g);
        }
    };

    #pragma unroll
    for (int i = 0; i < 4; i++)
        #pragma unroll
        for (int j = 0; j < 4; j++)
            #pragma unroll
            for (int k = 0; k < 4; k++) acc[i][j][k] = 0.f;

    load_stage(0, smem);
    cp_commit();
    load_stage(64, smem + STAGE_BYTES);
    cp_commit();
    cp_wait1();
    __syncthreads();

    const int arow = warp_m * 64 + (lane & 15);
    const int ah_  = lane >> 4;
    const int brow = warp_n * 32 + ((lane >> 4) << 3) + (lane & 7);
    const int bkh  = (lane >> 3) & 1;

    for (int ks = 0; ks < NSTAGE; ks++) {
        const uint32_t sb = smem + (ks & 1) * STAGE_BYTES;

        #pragma unroll
        for (int kk = 0; kk < 4; kk++) {
            uint32_t ahf[4][4], alf[4][4], bhf[4][2], blf[4][2];
            #pragma unroll
            for (int mt = 0; mt < 4; mt++) {
                const int r = arow + mt * 16;
                const uint32_t off = r * 128 + ((((kk << 1) | ah_) ^ (r & 7)) << 4);
                LDSM4(ahf[mt], sb + off);
                LDSM4(alf[mt], sb + MAT_BYTES + off);
            }
            #pragma unroll
            for (int np = 0; np < 2; np++) {
                const int r = brow + np * 16;
                const uint32_t off = r * 128 + ((((kk << 1) | bkh) ^ (r & 7)) << 4);
                uint32_t q[4];
                LDSM4(q, sb + 2 * MAT_BYTES + off);
                bhf[np * 2 + 0][0] = q[0];  bhf[np * 2 + 0][1] = q[1];
                bhf[np * 2 + 1][0] = q[2];  bhf[np * 2 + 1][1] = q[3];
                LDSM4(q, sb + 3 * MAT_BYTES + off);
                blf[np * 2 + 0][0] = q[0];  blf[np * 2 + 0][1] = q[1];
                blf[np * 2 + 1][0] = q[2];  blf[np * 2 + 1][1] = q[3];
            }
            #pragma unroll
            for (int mt = 0; mt < 4; mt++)
                #pragma unroll
                for (int nt = 0; nt < 4; nt++) {
                    mma16816(acc[mt][nt], ahf[mt], bhf[nt]);
                    mma16816(acc[mt][nt], ahf[mt], blf[nt]);
                    mma16816(acc[mt][nt], alf[mt], bhf[nt]);
                }
        }

        __syncthreads();
        if (ks + 2 < NSTAGE)
            load_stage((ks + 2) * 64, sb);
        cp_commit();
        cp_wait1();
        __syncthreads();
    }
}

// QKV GEMM with fused epilogue: head-major bf16 hi/lo (Q scaled 0.125),
// V transposed through smem.
__global__ __launch_bounds__(256, 1)
void qkv_gemm_tc()
{
    extern __shared__ __align__(128) char smem_raw[];
    const uint32_t smem = smem_u32(smem_raw);
    const int m0 = blockIdx.y * 128;
    const int n0 = blockIdx.x * 128;

    float acc[4][4][4];
    gemm_mainloop(g_xhi, g_xlo, g_wahi, g_walo, m0, n0, smem, acc);

    const int tid  = threadIdx.x;
    const int lane = tid & 31;
    const int warp = tid >> 5;
    const int warp_m = warp & 1;
    const int warp_n = warp >> 1;
    const int g  = lane >> 2;
    const int tg = lane & 3;
    const int bb = m0 >> 11;
    const int t0 = m0 & 2047;

    const int sect = n0 >> 10;       // 0=Q, 1=K, 2=V
    if (sect < 2) {
        const float sc = (sect == 0) ? 0.125f : 1.f;
        __nv_bfloat16* hi = (sect == 0) ? g_qh : g_kh;
        __nv_bfloat16* lo = (sect == 0) ? g_ql : g_kl;
        const int nc = n0 & 1023;
        #pragma unroll
        for (int mt = 0; mt < 4; mt++) {
            #pragma unroll
            for (int nt = 0; nt < 4; nt++) {
                const int c  = nc + warp_n * 32 + nt * 8 + tg * 2;
                const int hh = c >> 6, d = c & 63;
                const int r  = warp_m * 64 + mt * 16 + g;
                const size_t base = ((size_t)(bb * H_ + hh) * T_ + t0 + r) * DH + d;
                __nv_bfloat16 h0, h1, h2, h3, l0, l1, l2, l3;
                split2(acc[mt][nt][0] * sc, h0, l0);
                split2(acc[mt][nt][1] * sc, h1, l1);
                split2(acc[mt][nt][2] * sc, h2, l2);
                split2(acc[mt][nt][3] * sc, h3, l3);
                *(__nv_bfloat162*)(hi + base) = __halves2bfloat162(h0, h1);
                *(__nv_bfloat162*)(lo + base) = __halves2bfloat162(l0, l1);
                *(__nv_bfloat162*)(hi + base + 8 * DH) = __halves2bfloat162(h2, h3);
                *(__nv_bfloat162*)(lo + base + 8 * DH) = __halves2bfloat162(l2, l3);
            }
        }
    } else {
        // V: transpose 128x128 tile through smem (stride 130: conflict-free)
        cp_wait0();
        __syncthreads();
        float* sf = (float*)smem_raw;
        #pragma unroll
        for (int mt = 0; mt < 4; mt++) {
            #pragma unroll
            for (int nt = 0; nt < 4; nt++) {
                const int r = warp_m * 64 + mt * 16 + g;
                const int c = warp_n * 32 + nt * 8 + tg * 2;
                sf[r * 130 + c]           = acc[mt][nt][0];
                sf[r * 130 + c + 1]       = acc[mt][nt][1];
                sf[(r + 8) * 130 + c]     = acc[mt][nt][2];
                sf[(r + 8) * 130 + c + 1] = acc[mt][nt][3];
            }
        }
        __syncthreads();
        const int dl = tid & 127;     // column within tile (d)
        const int th = tid >> 7;      // t-half
        const int nv = (n0 - 2048) + dl;
        const int hh = nv >> 6, d = nv & 63;
        const size_t ob = ((size_t)(bb * H_ + hh) * DH + d) * T_ + t0 + th * 64;
        #pragma unroll
        for (int i = 0; i < 64; i += 2) {
            const float v0 = sf[(th * 64 + i) * 130 + dl];
            const float v1 = sf[(th * 64 + i + 1) * 130 + dl];
            __nv_bfloat16 h0, h1, l0, l1;
            split2(v0, h0, l0);
            split2(v1, h1, l1);
            *(__nv_bfloat162*)(g_vth + ob + i) = __halves2bfloat162(h0, h1);
            *(__nv_bfloat162*)(g_vtl + ob + i) = __halves2bfloat162(l0, l1);
        }
    }
}

// proj GEMM: plain fp32 epilogue to d_out
__global__ __launch_bounds__(256, 1)
void proj_gemm_tc(float* __restrict__ out)
{
    extern __shared__ __align__(128) char smem_raw[];
    const uint32_t smem = smem_u32(smem_raw);
    const int m0 = blockIdx.y * 128;
    const int n0 = blockIdx.x * 128;

    float acc[4][4][4];
    gemm_mainloop(g_yhi, g_ylo, g_wphi, g_wplo, m0, n0, smem, acc);

    const int lane = threadIdx.x & 31;
    const int warp = threadIdx.x >> 5;
    const int warp_m = warp & 1;
    const int warp_n = warp >> 1;
    const int g  = lane >> 2;
    const int tg = lane & 3;
    #pragma unroll
    for (int mt = 0; mt < 4; mt++) {
        #pragma unroll
        for (int nt = 0; nt < 4; nt++) {
            const int row = m0 + warp_m * 64 + mt * 16 + g;
            const int col = n0 + warp_n * 32 + nt * 8 + tg * 2;
            *(float2*)(out + (size_t)row * C_ + col) =
                make_float2(acc[mt][nt][0], acc[mt][nt][1]);
            *(float2*)(out + (size_t)(row + 8) * C_ + col) =
                make_float2(acc[mt][nt][2], acc[mt][nt][3]);
        }
    }
}

// ---------------------------------------------------------------------------
// HMMA flash attention: CTA = 128 queries x one (b,h). **8 warps / 256 thr**
// (2 warps/SMSP for latency hiding). Warp owns 16 query rows.
// 3-buffer cp.async pipeline over K/V tiles of 64 keys.
// smem: Q hi/lo 32KB + 3 stages x 32KB = 128KB.
// ---------------------------------------------------------------------------
#define ATT_STAGE 32768
#define ATT_SMEM  (32768 + 3 * ATT_STAGE)

__global__ __launch_bounds__(256, 1)
void attn_hmma_kernel()
{
    extern __shared__ __align__(128) char smem_raw[];
    const uint32_t smem = smem_u32(smem_raw);
    const uint32_t qsm  = smem;
    const uint32_t st0  = smem + 32768;

    const int tid  = threadIdx.x;
    const int lane = tid & 31;
    const int warp = tid >> 5;                       // 0..7
    const int qt   = (gridDim.x - 1) - blockIdx.x;   // heavy first
    const int bh   = blockIdx.z * H_ + blockIdx.y;
    const size_t qkb = (size_t)bh * T_ * DH;
    const size_t vb  = (size_t)bh * DH * T_;
    const int nkt = 2 * (qt + 1);

    // Q tile load (once; 8 chunks/thread)
    {
        const __nv_bfloat16* s0 = g_qh + qkb + (size_t)qt * 128 * DH;
        const __nv_bfloat16* s1 = g_ql + qkb + (size_t)qt * 128 * DH;
        #pragma unroll
        for (int t = 0; t < 8; t++) {
            const int rem = ((t & 3) << 8) + tid;    // 0..1023
            const int row = rem >> 3, ch = tid & 7;
            const __nv_bfloat16* g = ((t >> 2) ? s1 : s0) + (size_t)row * DH + ch * 8;
            cp16(qsm + (t >> 2) * 16384 + row * 128 + ((ch ^ (row & 7)) << 4), g);
        }
    }
    auto load_kv = [&](int kt, uint32_t stage) {
        #pragma unroll
        for (int t = 0; t < 8; t++) {
            const int mat = t >> 1;
            const int rem = ((t & 1) << 8) + tid;    // 0..511
            const int row = rem >> 3, ch = tid & 7;
            const __nv_bfloat16* g;
            if (mat == 0)      g = g_kh  + qkb + (size_t)(kt * 64 + row) * DH + ch * 8;
            else if (mat == 1) g = g_kl  + qkb + (size_t)(kt * 64 + row) * DH + ch * 8;
            else if (mat == 2) g = g_vth + vb  + (size_t)row * T_ + kt * 64 + ch * 8;
            else               g = g_vtl + vb  + (size_t)row * T_ + kt * 64 + ch * 8;
            cp16(stage + mat * 8192 + row * 128 + ((ch ^ (row & 7)) << 4), g);
        }
    };

    load_kv(0, st0);
    cp_commit();                 // group: Q + kv0
    load_kv(1, st0 + ATT_STAGE);
    cp_commit();                 // group: kv1

    const int g   = lane >> 2;
    const int c2  = (lane & 3) * 2;
    const int q0w = qt * 128 + warp * 16;
    const int bkh = (lane >> 3) & 1;
    const int ah_ = lane >> 4;
    const int brow_base = ((lane >> 4) << 3) + (lane & 7);

    float O[8][4];
    #pragma unroll
    for (int nt = 0; nt < 8; nt++)
        #pragma unroll
        for (int i = 0; i < 4; i++) O[nt][i] = 0.f;
    float mrun0 = -1e30f, mrun1 = -1e30f;
    float lrun0 = 0.f, lrun1 = 0.f;

    for (int kt = 0; kt < nkt; kt++) {
        cp_wait1();
        __syncthreads();

        // prefetch kt+2 into the buffer freed by the barrier
        const uint32_t nb = st0 + ((kt + 2) % 3) * ATT_STAGE;
        if (kt + 2 < nkt) load_kv(kt + 2, nb);
        else              cp16(nb + tid * 16, g_kh + tid * 8);   // real dummy
        cp_commit();

        const uint32_t sb = st0 + (kt % 3) * ATT_STAGE;

        float sacc[8][4];
        #pragma unroll
        for (int nt = 0; nt < 8; nt++)
            #pragma unroll
            for (int i = 0; i < 4; i++) sacc[nt][i] = 0.f;

        // ---- S = Q K^T (bf16x3) ----
        #pragma unroll
        for (int kk = 0; kk < 4; kk++) {
            uint32_t qhf[4], qlf[4];
            {
                const int r = warp * 16 + (lane & 15);
                const uint32_t off = r * 128 + ((((kk << 1) | ah_) ^ (r & 7)) << 4);
                LDSM4(qhf, qsm + off);
                LDSM4(qlf, qsm + 16384 + off);
            }
            uint32_t khf[8][2], klf[8][2];
            #pragma unroll
            for (int np = 0; np < 4; np++) {
                const int r = np * 16 + brow_base;
                const uint32_t off = r * 128 + ((((kk << 1) | bkh) ^ (r & 7)) << 4);
                uint32_t q4[4];
                LDSM4(q4, sb + off);
                khf[np * 2 + 0][0] = q4[0];  khf[np * 2 + 0][1] = q4[1];
                khf[np * 2 + 1][0] = q4[2];  khf[np * 2 + 1][1] = q4[3];
                LDSM4(q4, sb + 8192 + off);
                klf[np * 2 + 0][0] = q4[0];  klf[np * 2 + 0][1] = q4[1];
                klf[np * 2 + 1][0] = q4[2];  klf[np * 2 + 1][1] = q4[3];
            }
            #pragma unroll
            for (int nt = 0; nt < 8; nt++) {
                mma16816(sacc[nt], qhf, khf[nt]);
                mma16816(sacc[nt], qhf, klf[nt]);
                mma16816(sacc[nt], qlf, khf[nt]);
            }
        }

        // ---- causal mask (diagonal tiles only) ----
        if (kt >= 2 * qt) {
            const int kt64 = kt * 64;
            const int qr0 = q0w + g;
            #pragma unroll
            for (int nt = 0; nt < 8; nt++) {
                const int kc = kt64 + nt * 8 + c2;
                if (kc > qr0)         sacc[nt][0] = -1e30f;
                if (kc + 1 > qr0)     sacc[nt][1] = -1e30f;
                if (kc > qr0 + 8)     sacc[nt][2] = -1e30f;
                if (kc + 1 > qr0 + 8) sacc[nt][3] = -1e30f;
            }
        }

        // ---- online softmax ----
        {
            float h0 = -1e30f, h1 = -1e30f;
            #pragma unroll
            for (int nt = 0; nt < 8; nt++) {
                h0 = fmaxf(h0, fmaxf(sacc[nt][0], sacc[nt][1]));
                h1 = fmaxf(h1, fmaxf(sacc[nt][2], sacc[nt][3]));
            }
            h0 = fmaxf(h0, __shfl_xor_sync(0xffffffffu, h0, 1));
            h0 = fmaxf(h0, __shfl_xor_sync(0xffffffffu, h0, 2));
            h1 = fmaxf(h1, __shfl_xor_sync(0xffffffffu, h1, 1));
            h1 = fmaxf(h1, __shfl_xor_sync(0xffffffffu, h1, 2));
            const float m0 = fmaxf(mrun0, h0);
            const float m1 = fmaxf(mrun1, h1);
            const float a0 = __expf(mrun0 - m0);
            const float a1 = __expf(mrun1 - m1);
            mrun0 = m0;  mrun1 = m1;

            float s0 = 0.f, s1 = 0.f;
            #pragma unroll
            for (int nt = 0; nt < 8; nt++) {
                float p0 = __expf(sacc[nt][0] - m0);
                float p1 = __expf(sacc[nt][1] - m0);
                float p2 = __expf(sacc[nt][2] - m1);
                float p3 = __expf(sacc[nt][3] - m1);
                sacc[nt][0] = p0;  sacc[nt][1] = p1;
                sacc[nt][2] = p2;  sacc[nt][3] = p3;
                s0 += p0 + p1;
                s1 += p2 + p3;
            }
            s0 += __shfl_xor_sync(0xffffffffu, s0, 1);
            s0 += __shfl_xor_sync(0xffffffffu, s0, 2);
            s1 += __shfl_xor_sync(0xffffffffu, s1, 1);
            s1 += __shfl_xor_sync(0xffffffffu, s1, 2);
            lrun0 = lrun0 * a0 + s0;
            lrun1 = lrun1 * a1 + s1;

            #pragma unroll
            for (int nt = 0; nt < 8; nt++) {
                O[nt][0] *= a0;
                O[nt][1] *= a0;
                O[nt][2] *= a1;
                O[nt][3] *= a1;
            }
        }

        // ---- O += P V (bf16x3, P hi/lo in registers) ----
        #pragma unroll
        for (int kc = 0; kc < 4; kc++) {
            uint32_t ph[4], pl[4];
            #pragma unroll
            for (int half = 0; half < 2; half++) {
                const int nt = 2 * kc + half;
                float p0 = sacc[nt][0], p1 = sacc[nt][1];
                float p2 = sacc[nt][2], p3 = sacc[nt][3];
                float h0 = __bfloat162float(__float2bfloat16(p0));
                float h1 = __bfloat162float(__float2bfloat16(p1));
                float h2 = __bfloat162float(__float2bfloat16(p2));
                float h3 = __bfloat162float(__float2bfloat16(p3));
                ph[half * 2 + 0] = pack_bf16x2(h0, h1);
                ph[half * 2 + 1] = pack_bf16x2(h2, h3);
                pl[half * 2 + 0] = pack_bf16x2(p0 - h0, p1 - h1);
                pl[half * 2 + 1] = pack_bf16x2(p2 - h2, p3 - h3);
            }
            uint32_t vh[8][2], vl[8][2];
            #pragma unroll
            for (int np = 0; np < 4; np++) {
                const int r = np * 16 + brow_base;
                const uint32_t off = r * 128 + ((((kc << 1) | bkh) ^ (r & 7)) << 4);
                uint32_t q4[4];
                LDSM4(q4, sb + 16384 + off);
                vh[np * 2 + 0][0] = q4[0];  vh[np * 2 + 0][1] = q4[1];
                vh[np * 2 + 1][0] = q4[2];  vh[np * 2 + 1][1] = q4[3];
                LDSM4(q4, sb + 24576 + off);
                vl[np * 2 + 0][0] = q4[0];  vl[np * 2 + 0][1] = q4[1];
                vl[np * 2 + 1][0] = q4[2];  vl[np * 2 + 1][1] = q4[3];
            }
            #pragma unroll
            for (int nt = 0; nt < 8; nt++) {
                mma16816(O[nt], ph, vh[nt]);
                mma16816(O[nt], ph, vl[nt]);
                mma16816(O[nt], pl, vh[nt]);
            }
        }
    }

    // ---- epilogue: y = O / l, written as bf16 hi/lo for the proj GEMM ----
    const int hcol = blockIdx.y * 64;
    const float inv0 = 1.f / lrun0;
    const float inv1 = 1.f / lrun1;
    const int r0 = blockIdx.z * T_ + q0w + g;
    #pragma unroll
    for (int nt = 0; nt < 8; nt++) {
        const size_t o0 = (size_t)r0 * C_ + hcol + nt * 8 + c2;
        const size_t o1 = o0 + (size_t)8 * C_;
        __nv_bfloat16 h0, h1, h2, h3, l0, l1, l2, l3;
        split2(O[nt][0] * inv0, h0, l0);
        split2(O[nt][1] * inv0, h1, l1);
        split2(O[nt][2] * inv1, h2, l2);
        split2(O[nt][3] * inv1, h3, l3);
        *(__nv_bfloat162*)(g_yhi + o0) = __halves2bfloat162(h0, h1);
        *(__nv_bfloat162*)(g_ylo + o0) = __halves2bfloat162(l0, l1);
        *(__nv_bfloat162*)(g_yhi + o1) = __halves2bfloat162(h2, h3);
        *(__nv_bfloat162*)(g_ylo + o1) = __halves2bfloat162(l2, l3);
    }
}

// ---------------------------------------------------------------------------
extern "C" void kernel_launch(void* const* d_in, const int* in_sizes, int n_in,
                              void* d_out, int out_size)
{
    const float* x      = (const float*)d_in[0];
    const float* w_attn = (const float*)d_in[1];
    const float* w_proj = (const float*)d_in[2];
    float* out = (float*)d_out;

    static bool attr_done = false;
    if (!attr_done) {
        cudaFuncSetAttribute(qkv_gemm_tc,  cudaFuncAttributeMaxDynamicSharedMemorySize, GEMM_SMEM);
        cudaFuncSetAttribute(proj_gemm_tc, cudaFuncAttributeMaxDynamicSharedMemorySize, GEMM_SMEM);
        cudaFuncSetAttribute(attn_hmma_kernel, cudaFuncAttributeMaxDynamicSharedMemorySize, ATT_SMEM);
        attr_done = true;
    }

    __nv_bfloat16 *xhi, *xlo, *wahi, *walo, *wphi, *wplo;
    cudaGetSymbolAddress((void**)&xhi,  g_xhi);
    cudaGetSymbolAddress((void**)&xlo,  g_xlo);
    cudaGetSymbolAddress((void**)&wahi, g_wahi);
    cudaGetSymbolAddress((void**)&walo, g_walo);
    cudaGetSymbolAddress((void**)&wphi, g_wphi);
    cudaGetSymbolAddress((void**)&wplo, g_wplo);

    // 1) split x -> bf16 hi/lo
    split_kernel<<<(M_ * KD) / 1024, 256>>>(x, xhi, xlo, M_ * KD);
    // 2) transpose+split weights
    {
        dim3 grid(KD / 32, (3 * C_) / 32);
        splitT_kernel<<<grid, dim3(32, 8)>>>(w_attn, wahi, walo, KD, 3 * C_);
    }
    {
        dim3 grid(KD / 32, C_ / 32);
        splitT_kernel<<<grid, dim3(32, 8)>>>(w_proj, wphi, wplo, KD, C_);
    }
    // 3) QKV GEMM (HMMA bf16x3, CTA 128x128) with fused head-major epilogue
    {
        dim3 grid((3 * C_) / 128, M_ / 128);
        qkv_gemm_tc<<<grid, 256, GEMM_SMEM>>>();
    }
    // 4) HMMA flash attention (8 warps) -> g_yhi/g_ylo
    {
        dim3 grid(T_ / 128, H_, B_);
        attn_hmma_kernel<<<grid, 256, ATT_SMEM>>>();
    }
    // 5) proj GEMM (HMMA bf16x3, CTA 128x128) -> out
    {
        dim3 grid(C_ / 128, M_ / 128);
        proj_gemm_tc<<<grid, 256, GEMM_SMEM>>>(out);
    }
}

// round 9
// speedup vs baseline: 1.3993x; 1.3993x over previous
#include <cuda_runtime.h>
#include <cuda_fp16.h>
#include <cstdint>

#define B_  2
#define T_  2048
#define C_  1024
#define H_  16
#define DH  64
#define M_  (B_ * T_)
#define KD  1024

// ---------------- scratch (static device globals) ----------------
__device__ __half g_xhi[(size_t)M_ * KD];
__device__ __half g_xlo[(size_t)M_ * KD];
__device__ __half g_wah[(size_t)3 * C_ * KD];    // W_attn^T [3072,1024] single fp16
__device__ __half g_wph[(size_t)C_ * KD];        // W_proj^T [1024,1024] single fp16
__device__ __half g_yhi[(size_t)M_ * KD];        // attention out (hi)
__device__ __half g_ylo[(size_t)M_ * KD];        // attention out (lo)
// head-major attention operands (written by fused QKV epilogue)
__device__ __half g_qh[(size_t)B_ * H_ * T_ * DH];
__device__ __half g_ql[(size_t)B_ * H_ * T_ * DH];
__device__ __half g_kh[(size_t)B_ * H_ * T_ * DH];          // K single fp16
__device__ __half g_vth[(size_t)B_ * H_ * DH * T_];         // V^T single fp16 [bh][d][t]

// ---------------- base-ISA PTX helpers (sm_80+) ----------------
__device__ __forceinline__ uint32_t smem_u32(const void* p) {
    uint32_t a;
    asm("{ .reg .u64 t; cvta.to.shared.u64 t, %1; cvt.u32.u64 %0, t; }" : "=r"(a) : "l"(p));
    return a;
}
__device__ __forceinline__ void cp16(uint32_t s, const void* g) {
    asm volatile("cp.async.cg.shared.global [%0], [%1], 16;" :: "r"(s), "l"(g));
}
__device__ __forceinline__ void cp_commit() {
    asm volatile("cp.async.commit_group;" ::: "memory");
}
__device__ __forceinline__ void cp_wait1() {
    asm volatile("cp.async.wait_group 1;" ::: "memory");
}
__device__ __forceinline__ void cp_wait0() {
    asm volatile("cp.async.wait_group 0;" ::: "memory");
}
#define LDSM4(R, addr) \
    asm volatile("ldmatrix.sync.aligned.m8n8.x4.shared.b16 {%0,%1,%2,%3}, [%4];" \
                 : "=r"((R)[0]), "=r"((R)[1]), "=r"((R)[2]), "=r"((R)[3]) : "r"(addr))

__device__ __forceinline__ void mma16816(float* c, const uint32_t* a, const uint32_t* b) {
    asm volatile(
        "mma.sync.aligned.m16n8k16.row.col.f32.f16.f16.f32 "
        "{%0,%1,%2,%3}, {%4,%5,%6,%7}, {%8,%9}, {%0,%1,%2,%3};"
        : "+f"(c[0]), "+f"(c[1]), "+f"(c[2]), "+f"(c[3])
        : "r"(a[0]), "r"(a[1]), "r"(a[2]), "r"(a[3]), "r"(b[0]), "r"(b[1]));
}
// pack two fp32 -> f16x2 reg, lo in low half
__device__ __forceinline__ uint32_t pack_f16x2(float lo, float hi) {
    uint32_t d;
    asm("cvt.rn.f16x2.f32 %0, %1, %2;" : "=r"(d) : "f"(hi), "f"(lo));
    return d;
}

// ---------------- fp32 -> fp16 hi/lo split ----------------
__device__ __forceinline__ void split2h(float v, __half& h, __half& l) {
    h = __float2half(v);
    l = __float2half(v - __half2float(h));
}

__global__ __launch_bounds__(256)
void split_kernel(const float* __restrict__ in,
                  __half* __restrict__ hi, __half* __restrict__ lo, int n)
{
    int i = (blockIdx.x * 256 + threadIdx.x) * 4;
    if (i >= n) return;
    float4 v = *(const float4*)(in + i);
    __half h0, h1, h2, h3, l0, l1, l2, l3;
    split2h(v.x, h0, l0); split2h(v.y, h1, l1);
    split2h(v.z, h2, l2); split2h(v.w, h3, l3);
    *(__half2*)(hi + i)     = __halves2half2(h0, h1);
    *(__half2*)(hi + i + 2) = __halves2half2(h2, h3);
    *(__half2*)(lo + i)     = __halves2half2(l0, l1);
    *(__half2*)(lo + i + 2) = __halves2half2(l2, l3);
}

// transpose + convert: W fp32 [Kdim, Ndim] -> W^T single fp16 [Ndim, Kdim]
__global__ __launch_bounds__(256)
void convT_kernel(const float* __restrict__ W, __half* __restrict__ WT,
                  int Kdim, int Ndim)
{
    __shared__ float tile[32][33];
    const int k0 = blockIdx.x * 32, n0 = blockIdx.y * 32;
    const int tx = threadIdx.x, ty = threadIdx.y;   // 32 x 8
    #pragma unroll
    for (int i = 0; i < 32; i += 8)
        tile[ty + i][tx] = W[(size_t)(k0 + ty + i) * Ndim + n0 + tx];
    __syncthreads();
    #pragma unroll
    for (int i = 0; i < 32; i += 8) {
        WT[(size_t)(n0 + ty + i) * Kdim + k0 + tx] = __float2half(tile[tx][ty + i]);
    }
}

// ---------------------------------------------------------------------------
// fp16x2 HMMA GEMM mainloop: C = (Ahi+Alo) * Bh^T (fp32 accum).
// CTA 128x128, 8 warps 2(M) x 4(N), warp tile 64x32, BK=64,
// 2-stage cp.async pipeline. Stage: Ahi 16K | Alo 16K | Bh 16K = 48KB.
// ---------------------------------------------------------------------------
#define MAT_BYTES   16384
#define STAGE_BYTES (3 * MAT_BYTES)
#define GEMM_SMEM   (2 * STAGE_BYTES)
#define NSTAGE      (KD / 64)

__device__ __forceinline__ void gemm_mainloop(
    const __half* __restrict__ Ahi, const __half* __restrict__ Alo,
    const __half* __restrict__ Bh,
    int m0, int n0, uint32_t smem, float (&acc)[4][4][4])
{
    const int tid    = threadIdx.x;
    const int lane   = tid & 31;
    const int warp   = tid >> 5;
    const int warp_m = warp & 1;
    const int warp_n = warp >> 1;

    const __half* mats[3] = { Ahi, Alo, Bh };
    const int rowbase[3] = { m0, m0, n0 };

    auto load_stage = [&](int kofs, uint32_t stage_u32) {
        #pragma unroll
        for (int t = 0; t < 12; t++) {
            const int mat = t >> 2;
            const int rem = ((t & 3) << 8) + tid;
            const int row = rem >> 3;
            const int ch  = tid & 7;
            const __half* g = mats[mat]
                + (size_t)(rowbase[mat] + row) * KD + kofs + ch * 8;
            uint32_t s = stage_u32 + mat * MAT_BYTES + row * 128
                       + ((ch ^ (row & 7)) << 4);
            cp16(s, g);
        }
    };

    #pragma unroll
    for (int i = 0; i < 4; i++)
        #pragma unroll
        for (int j = 0; j < 4; j++)
            #pragma unroll
            for (int k = 0; k < 4; k++) acc[i][j][k] = 0.f;

    load_stage(0, smem);
    cp_commit();
    load_stage(64, smem + STAGE_BYTES);
    cp_commit();
    cp_wait1();
    __syncthreads();

    const int arow = warp_m * 64 + (lane & 15);
    const int ah_  = lane >> 4;
    const int brow = warp_n * 32 + ((lane >> 4) << 3) + (lane & 7);
    const int bkh  = (lane >> 3) & 1;

    for (int ks = 0; ks < NSTAGE; ks++) {
        const uint32_t sb = smem + (ks & 1) * STAGE_BYTES;

        #pragma unroll
        for (int kk = 0; kk < 4; kk++) {
            uint32_t ahf[4][4], alf[4][4], bhf[4][2];
            #pragma unroll
            for (int mt = 0; mt < 4; mt++) {
                const int r = arow + mt * 16;
                const uint32_t off = r * 128 + ((((kk << 1) | ah_) ^ (r & 7)) << 4);
                LDSM4(ahf[mt], sb + off);
                LDSM4(alf[mt], sb + MAT_BYTES + off);
            }
            #pragma unroll
            for (int np = 0; np < 2; np++) {
                const int r = brow + np * 16;
                const uint32_t off = r * 128 + ((((kk << 1) | bkh) ^ (r & 7)) << 4);
                uint32_t q[4];
                LDSM4(q, sb + 2 * MAT_BYTES + off);
                bhf[np * 2 + 0][0] = q[0];  bhf[np * 2 + 0][1] = q[1];
                bhf[np * 2 + 1][0] = q[2];  bhf[np * 2 + 1][1] = q[3];
            }
            #pragma unroll
            for (int mt = 0; mt < 4; mt++)
                #pragma unroll
                for (int nt = 0; nt < 4; nt++) {
                    mma16816(acc[mt][nt], ahf[mt], bhf[nt]);
                    mma16816(acc[mt][nt], alf[mt], bhf[nt]);
                }
        }

        __syncthreads();
        if (ks + 2 < NSTAGE)
            load_stage((ks + 2) * 64, sb);
        cp_commit();
        cp_wait1();
        __syncthreads();
    }
}

// QKV GEMM with fused epilogue: Q -> hi/lo fp16 (scaled 0.125), K -> single
// fp16 head-major, V -> single fp16 transposed through smem.
__global__ __launch_bounds__(256, 2)
void qkv_gemm_tc()
{
    extern __shared__ __align__(128) char smem_raw[];
    const uint32_t smem = smem_u32(smem_raw);
    const int m0 = blockIdx.y * 128;
    const int n0 = blockIdx.x * 128;

    float acc[4][4][4];
    gemm_mainloop(g_xhi, g_xlo, g_wah, m0, n0, smem, acc);

    const int tid  = threadIdx.x;
    const int lane = tid & 31;
    const int warp = tid >> 5;
    const int warp_m = warp & 1;
    const int warp_n = warp >> 1;
    const int g  = lane >> 2;
    const int tg = lane & 3;
    const int bb = m0 >> 11;
    const int t0 = m0 & 2047;

    const int sect = n0 >> 10;       // 0=Q, 1=K, 2=V
    if (sect == 0) {
        const int nc = n0 & 1023;
        #pragma unroll
        for (int mt = 0; mt < 4; mt++) {
            #pragma unroll
            for (int nt = 0; nt < 4; nt++) {
                const int c  = nc + warp_n * 32 + nt * 8 + tg * 2;
                const int hh = c >> 6, d = c & 63;
                const int r  = warp_m * 64 + mt * 16 + g;
                const size_t base = ((size_t)(bb * H_ + hh) * T_ + t0 + r) * DH + d;
                __half h0, h1, h2, h3, l0, l1, l2, l3;
                split2h(acc[mt][nt][0] * 0.125f, h0, l0);
                split2h(acc[mt][nt][1] * 0.125f, h1, l1);
                split2h(acc[mt][nt][2] * 0.125f, h2, l2);
                split2h(acc[mt][nt][3] * 0.125f, h3, l3);
                *(__half2*)(g_qh + base) = __halves2half2(h0, h1);
                *(__half2*)(g_ql + base) = __halves2half2(l0, l1);
                *(__half2*)(g_qh + base + 8 * DH) = __halves2half2(h2, h3);
                *(__half2*)(g_ql + base + 8 * DH) = __halves2half2(l2, l3);
            }
        }
    } else if (sect == 1) {
        const int nc = n0 & 1023;
        #pragma unroll
        for (int mt = 0; mt < 4; mt++) {
            #pragma unroll
            for (int nt = 0; nt < 4; nt++) {
                const int c  = nc + warp_n * 32 + nt * 8 + tg * 2;
                const int hh = c >> 6, d = c & 63;
                const int r  = warp_m * 64 + mt * 16 + g;
                const size_t base = ((size_t)(bb * H_ + hh) * T_ + t0 + r) * DH + d;
                *(__half2*)(g_kh + base) =
                    __halves2half2(__float2half(acc[mt][nt][0]), __float2half(acc[mt][nt][1]));
                *(__half2*)(g_kh + base + 8 * DH) =
                    __halves2half2(__float2half(acc[mt][nt][2]), __float2half(acc[mt][nt][3]));
            }
        }
    } else {
        // V: transpose 128x128 tile through smem (stride 130: conflict-free)
        cp_wait0();
        __syncthreads();
        float* sf = (float*)smem_raw;
        #pragma unroll
        for (int mt = 0; mt < 4; mt++) {
            #pragma unroll
            for (int nt = 0; nt < 4; nt++) {
                const int r = warp_m * 64 + mt * 16 + g;
                const int c = warp_n * 32 + nt * 8 + tg * 2;
                sf[r * 130 + c]           = acc[mt][nt][0];
                sf[r * 130 + c + 1]       = acc[mt][nt][1];
                sf[(r + 8) * 130 + c]     = acc[mt][nt][2];
                sf[(r + 8) * 130 + c + 1] = acc[mt][nt][3];
            }
        }
        __syncthreads();
        const int dl = tid & 127;     // column within tile (d)
        const int th = tid >> 7;      // t-half
        const int nv = (n0 - 2048) + dl;
        const int hh = nv >> 6, d = nv & 63;
        const size_t ob = ((size_t)(bb * H_ + hh) * DH + d) * T_ + t0 + th * 64;
        #pragma unroll
        for (int i = 0; i < 64; i += 2) {
            const float v0 = sf[(th * 64 + i) * 130 + dl];
            const float v1 = sf[(th * 64 + i + 1) * 130 + dl];
            *(__half2*)(g_vth + ob + i) =
                __halves2half2(__float2half(v0), __float2half(v1));
        }
    }
}

// proj GEMM: plain fp32 epilogue to d_out
__global__ __launch_bounds__(256, 2)
void proj_gemm_tc(float* __restrict__ out)
{
    extern __shared__ __align__(128) char smem_raw[];
    const uint32_t smem = smem_u32(smem_raw);
    const int m0 = blockIdx.y * 128;
    const int n0 = blockIdx.x * 128;

    float acc[4][4][4];
    gemm_mainloop(g_yhi, g_ylo, g_wph, m0, n0, smem, acc);

    const int lane = threadIdx.x & 31;
    const int warp = threadIdx.x >> 5;
    const int warp_m = warp & 1;
    const int warp_n = warp >> 1;
    const int g  = lane >> 2;
    const int tg = lane & 3;
    #pragma unroll
    for (int mt = 0; mt < 4; mt++) {
        #pragma unroll
        for (int nt = 0; nt < 4; nt++) {
            const int row = m0 + warp_m * 64 + mt * 16 + g;
            const int col = n0 + warp_n * 32 + nt * 8 + tg * 2;
            *(float2*)(out + (size_t)row * C_ + col) =
                make_float2(acc[mt][nt][0], acc[mt][nt][1]);
            *(float2*)(out + (size_t)(row + 8) * C_ + col) =
                make_float2(acc[mt][nt][2], acc[mt][nt][3]);
        }
    }
}

// ---------------------------------------------------------------------------
// fp16x2 HMMA flash attention: CTA = 128 queries x one (b,h), 8 warps.
// Warp owns 16 query rows. QK: Q hi/lo x K single. PV: P hi/lo x V single.
// 3-buffer cp.async pipeline over K/V tiles of 64 keys.
// smem: Q hi/lo 32KB + 3 stages x 16KB = 80KB.
// ---------------------------------------------------------------------------
#define ATT_STAGE 16384
#define ATT_SMEM  (32768 + 3 * ATT_STAGE)

__global__ __launch_bounds__(256, 2)
void attn_hmma_kernel()
{
    extern __shared__ __align__(128) char smem_raw[];
    const uint32_t smem = smem_u32(smem_raw);
    const uint32_t qsm  = smem;
    const uint32_t st0  = smem + 32768;

    const int tid  = threadIdx.x;
    const int lane = tid & 31;
    const int warp = tid >> 5;                       // 0..7
    const int qt   = (gridDim.x - 1) - blockIdx.x;   // heavy first
    const int bh   = blockIdx.z * H_ + blockIdx.y;
    const size_t qkb = (size_t)bh * T_ * DH;
    const size_t vb  = (size_t)bh * DH * T_;
    const int nkt = 2 * (qt + 1);

    // Q tile load (once; hi then lo)
    {
        const __half* s0 = g_qh + qkb + (size_t)qt * 128 * DH;
        const __half* s1 = g_ql + qkb + (size_t)qt * 128 * DH;
        #pragma unroll
        for (int t = 0; t < 8; t++) {
            const int rem = ((t & 3) << 8) + tid;    // 0..1023
            const int row = rem >> 3, ch = tid & 7;
            const __half* g = ((t >> 2) ? s1 : s0) + (size_t)row * DH + ch * 8;
            cp16(qsm + (t >> 2) * 16384 + row * 128 + ((ch ^ (row & 7)) << 4), g);
        }
    }
    auto load_kv = [&](int kt, uint32_t stage) {
        #pragma unroll
        for (int t = 0; t < 4; t++) {
            const int mat = t >> 1;                  // 0=Kh, 1=Vth
            const int rem = ((t & 1) << 8) + tid;    // 0..511
            const int row = rem >> 3, ch = tid & 7;
            const __half* g = (mat == 0)
                ? g_kh  + qkb + (size_t)(kt * 64 + row) * DH + ch * 8
                : g_vth + vb  + (size_t)row * T_ + kt * 64 + ch * 8;
            cp16(stage + mat * 8192 + row * 128 + ((ch ^ (row & 7)) << 4), g);
        }
    };

    load_kv(0, st0);
    cp_commit();                 // group: Q + kv0
    load_kv(1, st0 + ATT_STAGE);
    cp_commit();                 // group: kv1

    const int g   = lane >> 2;
    const int c2  = (lane & 3) * 2;
    const int q0w = qt * 128 + warp * 16;
    const int bkh = (lane >> 3) & 1;
    const int ah_ = lane >> 4;
    const int brow_base = ((lane >> 4) << 3) + (lane & 7);

    float O[8][4];
    #pragma unroll
    for (int nt = 0; nt < 8; nt++)
        #pragma unroll
        for (int i = 0; i < 4; i++) O[nt][i] = 0.f;
    float mrun0 = -1e30f, mrun1 = -1e30f;
    float lrun0 = 0.f, lrun1 = 0.f;

    for (int kt = 0; kt < nkt; kt++) {
        cp_wait1();
        __syncthreads();

        // prefetch kt+2 into the buffer freed by the barrier
        const uint32_t nb = st0 + ((kt + 2) % 3) * ATT_STAGE;
        if (kt + 2 < nkt) load_kv(kt + 2, nb);
        else              cp16(nb + tid * 16, g_kh + tid * 8);   // real dummy
        cp_commit();

        const uint32_t sb = st0 + (kt % 3) * ATT_STAGE;

        float sacc[8][4];
        #pragma unroll
        for (int nt = 0; nt < 8; nt++)
            #pragma unroll
            for (int i = 0; i < 4; i++) sacc[nt][i] = 0.f;

        // ---- S = Q K^T (fp16x2) ----
        #pragma unroll
        for (int kk = 0; kk < 4; kk++) {
            uint32_t qhf[4], qlf[4];
            {
                const int r = warp * 16 + (lane & 15);
                const uint32_t off = r * 128 + ((((kk << 1) | ah_) ^ (r & 7)) << 4);
                LDSM4(qhf, qsm + off);
                LDSM4(qlf, qsm + 16384 + off);
            }
            uint32_t khf[8][2];
            #pragma unroll
            for (int np = 0; np < 4; np++) {
                const int r = np * 16 + brow_base;
                const uint32_t off = r * 128 + ((((kk << 1) | bkh) ^ (r & 7)) << 4);
                uint32_t q4[4];
                LDSM4(q4, sb + off);
                khf[np * 2 + 0][0] = q4[0];  khf[np * 2 + 0][1] = q4[1];
                khf[np * 2 + 1][0] = q4[2];  khf[np * 2 + 1][1] = q4[3];
            }
            #pragma unroll
            for (int nt = 0; nt < 8; nt++) {
                mma16816(sacc[nt], qhf, khf[nt]);
                mma16816(sacc[nt], qlf, khf[nt]);
            }
        }

        // ---- causal mask (diagonal tiles only) ----
        if (kt >= 2 * qt) {
            const int kt64 = kt * 64;
            const int qr0 = q0w + g;
            #pragma unroll
            for (int nt = 0; nt < 8; nt++) {
                const int kc = kt64 + nt * 8 + c2;
                if (kc > qr0)         sacc[nt][0] = -1e30f;
                if (kc + 1 > qr0)     sacc[nt][1] = -1e30f;
                if (kc > qr0 + 8)     sacc[nt][2] = -1e30f;
                if (kc + 1 > qr0 + 8) sacc[nt][3] = -1e30f;
            }
        }

        // ---- online softmax ----
        {
            float h0 = -1e30f, h1 = -1e30f;
            #pragma unroll
            for (int nt = 0; nt < 8; nt++) {
                h0 = fmaxf(h0, fmaxf(sacc[nt][0], sacc[nt][1]));
                h1 = fmaxf(h1, fmaxf(sacc[nt][2], sacc[nt][3]));
            }
            h0 = fmaxf(h0, __shfl_xor_sync(0xffffffffu, h0, 1));
            h0 = fmaxf(h0, __shfl_xor_sync(0xffffffffu, h0, 2));
            h1 = fmaxf(h1, __shfl_xor_sync(0xffffffffu, h1, 1));
            h1 = fmaxf(h1, __shfl_xor_sync(0xffffffffu, h1, 2));
            const float m0 = fmaxf(mrun0, h0);
            const float m1 = fmaxf(mrun1, h1);
            const float a0 = __expf(mrun0 - m0);
            const float a1 = __expf(mrun1 - m1);
            mrun0 = m0;  mrun1 = m1;

            float s0 = 0.f, s1 = 0.f;
            #pragma unroll
            for (int nt = 0; nt < 8; nt++) {
                float p0 = __expf(sacc[nt][0] - m0);
                float p1 = __expf(sacc[nt][1] - m0);
                float p2 = __expf(sacc[nt][2] - m1);
                float p3 = __expf(sacc[nt][3] - m1);
                sacc[nt][0] = p0;  sacc[nt][1] = p1;
                sacc[nt][2] = p2;  sacc[nt][3] = p3;
                s0 += p0 + p1;
                s1 += p2 + p3;
            }
            s0 += __shfl_xor_sync(0xffffffffu, s0, 1);
            s0 += __shfl_xor_sync(0xffffffffu, s0, 2);
            s1 += __shfl_xor_sync(0xffffffffu, s1, 1);
            s1 += __shfl_xor_sync(0xffffffffu, s1, 2);
            lrun0 = lrun0 * a0 + s0;
            lrun1 = lrun1 * a1 + s1;

            #pragma unroll
            for (int nt = 0; nt < 8; nt++) {
                O[nt][0] *= a0;
                O[nt][1] *= a0;
                O[nt][2] *= a1;
                O[nt][3] *= a1;
            }
        }

        // ---- O += P V (fp16x2, P hi/lo in registers) ----
        #pragma unroll
        for (int kc = 0; kc < 4; kc++) {
            uint32_t ph[4], pl[4];
            #pragma unroll
            for (int half = 0; half < 2; half++) {
                const int nt = 2 * kc + half;
                float p0 = sacc[nt][0], p1 = sacc[nt][1];
                float p2 = sacc[nt][2], p3 = sacc[nt][3];
                float h0 = __half2float(__float2half(p0));
                float h1 = __half2float(__float2half(p1));
                float h2 = __half2float(__float2half(p2));
                float h3 = __half2float(__float2half(p3));
                ph[half * 2 + 0] = pack_f16x2(h0, h1);
                ph[half * 2 + 1] = pack_f16x2(h2, h3);
                pl[half * 2 + 0] = pack_f16x2(p0 - h0, p1 - h1);
                pl[half * 2 + 1] = pack_f16x2(p2 - h2, p3 - h3);
            }
            uint32_t vh[8][2];
            #pragma unroll
            for (int np = 0; np < 4; np++) {
                const int r = np * 16 + brow_base;
                const uint32_t off = r * 128 + ((((kc << 1) | bkh) ^ (r & 7)) << 4);
                uint32_t q4[4];
                LDSM4(q4, sb + 8192 + off);
                vh[np * 2 + 0][0] = q4[0];  vh[np * 2 + 0][1] = q4[1];
                vh[np * 2 + 1][0] = q4[2];  vh[np * 2 + 1][1] = q4[3];
            }
            #pragma unroll
            for (int nt = 0; nt < 8; nt++) {
                mma16816(O[nt], ph, vh[nt]);
                mma16816(O[nt], pl, vh[nt]);
            }
        }
    }

    // ---- epilogue: y = O / l, written as fp16 hi/lo for the proj GEMM ----
    const int hcol = blockIdx.y * 64;
    const float inv0 = 1.f / lrun0;
    const float inv1 = 1.f / lrun1;
    const int r0 = blockIdx.z * T_ + q0w + g;
    #pragma unroll
    for (int nt = 0; nt < 8; nt++) {
        const size_t o0 = (size_t)r0 * C_ + hcol + nt * 8 + c2;
        const size_t o1 = o0 + (size_t)8 * C_;
        __half h0, h1, h2, h3, l0, l1, l2, l3;
        split2h(O[nt][0] * inv0, h0, l0);
        split2h(O[nt][1] * inv0, h1, l1);
        split2h(O[nt][2] * inv1, h2, l2);
        split2h(O[nt][3] * inv1, h3, l3);
        *(__half2*)(g_yhi + o0) = __halves2half2(h0, h1);
        *(__half2*)(g_ylo + o0) = __halves2half2(l0, l1);
        *(__half2*)(g_yhi + o1) = __halves2half2(h2, h3);
        *(__half2*)(g_ylo + o1) = __halves2half2(l2, l3);
    }
}

// ---------------------------------------------------------------------------
extern "C" void kernel_launch(void* const* d_in, const int* in_sizes, int n_in,
                              void* d_out, int out_size)
{
    const float* x      = (const float*)d_in[0];
    const float* w_attn = (const float*)d_in[1];
    const float* w_proj = (const float*)d_in[2];
    float* out = (float*)d_out;

    static bool attr_done = false;
    if (!attr_done) {
        cudaFuncSetAttribute(qkv_gemm_tc,  cudaFuncAttributeMaxDynamicSharedMemorySize, GEMM_SMEM);
        cudaFuncSetAttribute(proj_gemm_tc, cudaFuncAttributeMaxDynamicSharedMemorySize, GEMM_SMEM);
        cudaFuncSetAttribute(attn_hmma_kernel, cudaFuncAttributeMaxDynamicSharedMemorySize, ATT_SMEM);
        attr_done = true;
    }

    __half *xhi, *xlo, *wah, *wph;
    cudaGetSymbolAddress((void**)&xhi, g_xhi);
    cudaGetSymbolAddress((void**)&xlo, g_xlo);
    cudaGetSymbolAddress((void**)&wah, g_wah);
    cudaGetSymbolAddress((void**)&wph, g_wph);

    // 1) split x -> fp16 hi/lo
    split_kernel<<<(M_ * KD) / 1024, 256>>>(x, xhi, xlo, M_ * KD);
    // 2) transpose+convert weights to single fp16
    {
        dim3 grid(KD / 32, (3 * C_) / 32);
        convT_kernel<<<grid, dim3(32, 8)>>>(w_attn, wah, KD, 3 * C_);
    }
    {
        dim3 grid(KD / 32, C_ / 32);
        convT_kernel<<<grid, dim3(32, 8)>>>(w_proj, wph, KD, C_);
    }
    // 3) QKV GEMM (HMMA fp16x2) with fused head-major epilogue
    {
        dim3 grid((3 * C_) / 128, M_ / 128);
        qkv_gemm_tc<<<grid, 256, GEMM_SMEM>>>();
    }
    // 4) HMMA flash attention (fp16x2, 8 warps) -> g_yhi/g_ylo
    {
        dim3 grid(T_ / 128, H_, B_);
        attn_hmma_kernel<<<grid, 256, ATT_SMEM>>>();
    }
    // 5) proj GEMM (HMMA fp16x2) -> out
    {
        dim3 grid(C_ / 128, M_ / 128);
        proj_gemm_tc<<<grid, 256, GEMM_SMEM>>>(out);
    }
}

// round 10
// speedup vs baseline: 1.4010x; 1.0012x over previous
#include <cuda_runtime.h>
#include <cuda_fp16.h>
#include <cstdint>

#define B_  2
#define T_  2048
#define C_  1024
#define H_  16
#define DH  64
#define M_  (B_ * T_)
#define KD  1024

// ---------------- scratch (static device globals) ----------------
__device__ __half g_xhi[(size_t)M_ * KD];
__device__ __half g_xlo[(size_t)M_ * KD];
__device__ __half g_wah[(size_t)3 * C_ * KD];    // W_attn^T [3072,1024] single fp16
__device__ __half g_wph[(size_t)C_ * KD];        // W_proj^T [1024,1024] single fp16
__device__ __half g_yhi[(size_t)M_ * KD];        // attention out (hi)
__device__ __half g_ylo[(size_t)M_ * KD];        // attention out (lo)
// head-major attention operands (written by fused QKV epilogue)
__device__ __half g_qh[(size_t)B_ * H_ * T_ * DH];
__device__ __half g_ql[(size_t)B_ * H_ * T_ * DH];
__device__ __half g_kh[(size_t)B_ * H_ * T_ * DH];          // K single fp16
__device__ __half g_vth[(size_t)B_ * H_ * DH * T_];         // V^T single fp16 [bh][d][t]

// ---------------- base-ISA PTX helpers (sm_80+) ----------------
__device__ __forceinline__ uint32_t smem_u32(const void* p) {
    uint32_t a;
    asm("{ .reg .u64 t; cvta.to.shared.u64 t, %1; cvt.u32.u64 %0, t; }" : "=r"(a) : "l"(p));
    return a;
}
__device__ __forceinline__ void cp16(uint32_t s, const void* g) {
    asm volatile("cp.async.cg.shared.global [%0], [%1], 16;" :: "r"(s), "l"(g));
}
__device__ __forceinline__ void cp_commit() {
    asm volatile("cp.async.commit_group;" ::: "memory");
}
__device__ __forceinline__ void cp_wait1() {
    asm volatile("cp.async.wait_group 1;" ::: "memory");
}
__device__ __forceinline__ void cp_wait0() {
    asm volatile("cp.async.wait_group 0;" ::: "memory");
}
#define LDSM4(R, addr) \
    asm volatile("ldmatrix.sync.aligned.m8n8.x4.shared.b16 {%0,%1,%2,%3}, [%4];" \
                 : "=r"((R)[0]), "=r"((R)[1]), "=r"((R)[2]), "=r"((R)[3]) : "r"(addr))

__device__ __forceinline__ void mma16816(float* c, const uint32_t* a, const uint32_t* b) {
    asm volatile(
        "mma.sync.aligned.m16n8k16.row.col.f32.f16.f16.f32 "
        "{%0,%1,%2,%3}, {%4,%5,%6,%7}, {%8,%9}, {%0,%1,%2,%3};"
        : "+f"(c[0]), "+f"(c[1]), "+f"(c[2]), "+f"(c[3])
        : "r"(a[0]), "r"(a[1]), "r"(a[2]), "r"(a[3]), "r"(b[0]), "r"(b[1]));
}
// pack two fp32 -> f16x2 reg, lo in low half
__device__ __forceinline__ uint32_t pack_f16x2(float lo, float hi) {
    uint32_t d;
    asm("cvt.rn.f16x2.f32 %0, %1, %2;" : "=r"(d) : "f"(hi), "f"(lo));
    return d;
}

// ---------------- fp32 -> fp16 hi/lo split ----------------
__device__ __forceinline__ void split2h(float v, __half& h, __half& l) {
    h = __float2half(v);
    l = __float2half(v - __half2float(h));
}

__global__ __launch_bounds__(256)
void split_kernel(const float* __restrict__ in,
                  __half* __restrict__ hi, __half* __restrict__ lo, int n)
{
    int i = (blockIdx.x * 256 + threadIdx.x) * 4;
    if (i >= n) return;
    float4 v = *(const float4*)(in + i);
    __half h0, h1, h2, h3, l0, l1, l2, l3;
    split2h(v.x, h0, l0); split2h(v.y, h1, l1);
    split2h(v.z, h2, l2); split2h(v.w, h3, l3);
    *(__half2*)(hi + i)     = __halves2half2(h0, h1);
    *(__half2*)(hi + i + 2) = __halves2half2(h2, h3);
    *(__half2*)(lo + i)     = __halves2half2(l0, l1);
    *(__half2*)(lo + i + 2) = __halves2half2(l2, l3);
}

// transpose + convert: W fp32 [Kdim, Ndim] -> W^T single fp16 [Ndim, Kdim]
__global__ __launch_bounds__(256)
void convT_kernel(const float* __restrict__ W, __half* __restrict__ WT,
                  int Kdim, int Ndim)
{
    __shared__ float tile[32][33];
    const int k0 = blockIdx.x * 32, n0 = blockIdx.y * 32;
    const int tx = threadIdx.x, ty = threadIdx.y;   // 32 x 8
    #pragma unroll
    for (int i = 0; i < 32; i += 8)
        tile[ty + i][tx] = W[(size_t)(k0 + ty + i) * Ndim + n0 + tx];
    __syncthreads();
    #pragma unroll
    for (int i = 0; i < 32; i += 8) {
        WT[(size_t)(n0 + ty + i) * Kdim + k0 + tx] = __float2half(tile[tx][ty + i]);
    }
}

// ---------------------------------------------------------------------------
// fp16x2 HMMA GEMM mainloop: C = (Ahi+Alo) * Bh^T (fp32 accum).
// CTA 128x128, **4 warps 2(M) x 2(N), warp tile 64x64**, BK=64,
// 2-stage cp.async pipeline. Stage: Ahi 16K | Alo 16K | Bh 16K = 48KB.
// 128 threads, 2 CTAs/SM (regs effectively uncapped at 255).
// Feed ratio: 12 LDSM.x4 per kk for 64 HMMAs = 96 B/MMA.
// ---------------------------------------------------------------------------
#define MAT_BYTES   16384
#define STAGE_BYTES (3 * MAT_BYTES)
#define GEMM_SMEM   (2 * STAGE_BYTES)
#define NSTAGE      (KD / 64)

__device__ __forceinline__ void gemm_mainloop(
    const __half* __restrict__ Ahi, const __half* __restrict__ Alo,
    const __half* __restrict__ Bh,
    int m0, int n0, uint32_t smem, float (&acc)[4][8][4])
{
    const int tid    = threadIdx.x;      // 0..127
    const int lane   = tid & 31;
    const int warp   = tid >> 5;         // 0..3
    const int warp_m = warp & 1;
    const int warp_n = warp >> 1;        // 0..1

    const __half* mats[3] = { Ahi, Alo, Bh };
    const int rowbase[3] = { m0, m0, n0 };

    auto load_stage = [&](int kofs, uint32_t stage_u32) {
        #pragma unroll
        for (int t = 0; t < 24; t++) {
            const int mat = t >> 3;                   // compile-time
            const int rem = ((t & 7) << 7) + tid;     // 0..1023
            const int row = rem >> 3;
            const int ch  = tid & 7;
            const __half* g = mats[mat]
                + (size_t)(rowbase[mat] + row) * KD + kofs + ch * 8;
            uint32_t s = stage_u32 + mat * MAT_BYTES + row * 128
                       + ((ch ^ (row & 7)) << 4);
            cp16(s, g);
        }
    };

    #pragma unroll
    for (int i = 0; i < 4; i++)
        #pragma unroll
        for (int j = 0; j < 8; j++)
            #pragma unroll
            for (int k = 0; k < 4; k++) acc[i][j][k] = 0.f;

    load_stage(0, smem);
    cp_commit();
    load_stage(64, smem + STAGE_BYTES);
    cp_commit();
    cp_wait1();
    __syncthreads();

    const int arow = warp_m * 64 + (lane & 15);
    const int ah_  = lane >> 4;
    const int brow = warp_n * 64 + ((lane >> 4) << 3) + (lane & 7);
    const int bkh  = (lane >> 3) & 1;

    for (int ks = 0; ks < NSTAGE; ks++) {
        const uint32_t sb = smem + (ks & 1) * STAGE_BYTES;

        #pragma unroll
        for (int kk = 0; kk < 4; kk++) {
            uint32_t ahf[4][4], alf[4][4], bhf[8][2];
            #pragma unroll
            for (int mt = 0; mt < 4; mt++) {
                const int r = arow + mt * 16;
                const uint32_t off = r * 128 + ((((kk << 1) | ah_) ^ (r & 7)) << 4);
                LDSM4(ahf[mt], sb + off);
                LDSM4(alf[mt], sb + MAT_BYTES + off);
            }
            #pragma unroll
            for (int np = 0; np < 4; np++) {
                const int r = brow + np * 16;
                const uint32_t off = r * 128 + ((((kk << 1) | bkh) ^ (r & 7)) << 4);
                uint32_t q[4];
                LDSM4(q, sb + 2 * MAT_BYTES + off);
                bhf[np * 2 + 0][0] = q[0];  bhf[np * 2 + 0][1] = q[1];
                bhf[np * 2 + 1][0] = q[2];  bhf[np * 2 + 1][1] = q[3];
            }
            #pragma unroll
            for (int mt = 0; mt < 4; mt++)
                #pragma unroll
                for (int nt = 0; nt < 8; nt++) {
                    mma16816(acc[mt][nt], ahf[mt], bhf[nt]);
                    mma16816(acc[mt][nt], alf[mt], bhf[nt]);
                }
        }

        __syncthreads();
        if (ks + 2 < NSTAGE)
            load_stage((ks + 2) * 64, sb);
        cp_commit();
        cp_wait1();
        __syncthreads();
    }
}

// QKV GEMM with fused epilogue: Q -> hi/lo fp16 (scaled 0.125), K -> single
// fp16 head-major, V -> single fp16 transposed through smem.
__global__ __launch_bounds__(128, 2)
void qkv_gemm_tc()
{
    extern __shared__ __align__(128) char smem_raw[];
    const uint32_t smem = smem_u32(smem_raw);
    const int m0 = blockIdx.y * 128;
    const int n0 = blockIdx.x * 128;

    float acc[4][8][4];
    gemm_mainloop(g_xhi, g_xlo, g_wah, m0, n0, smem, acc);

    const int tid  = threadIdx.x;
    const int lane = tid & 31;
    const int warp = tid >> 5;
    const int warp_m = warp & 1;
    const int warp_n = warp >> 1;
    const int g  = lane >> 2;
    const int tg = lane & 3;
    const int bb = m0 >> 11;
    const int t0 = m0 & 2047;

    const int sect = n0 >> 10;       // 0=Q, 1=K, 2=V
    if (sect == 0) {
        const int nc = n0 & 1023;
        #pragma unroll
        for (int mt = 0; mt < 4; mt++) {
            #pragma unroll
            for (int nt = 0; nt < 8; nt++) {
                const int c  = nc + warp_n * 64 + nt * 8 + tg * 2;
                const int hh = c >> 6, d = c & 63;
                const int r  = warp_m * 64 + mt * 16 + g;
                const size_t base = ((size_t)(bb * H_ + hh) * T_ + t0 + r) * DH + d;
                __half h0, h1, h2, h3, l0, l1, l2, l3;
                split2h(acc[mt][nt][0] * 0.125f, h0, l0);
                split2h(acc[mt][nt][1] * 0.125f, h1, l1);
                split2h(acc[mt][nt][2] * 0.125f, h2, l2);
                split2h(acc[mt][nt][3] * 0.125f, h3, l3);
                *(__half2*)(g_qh + base) = __halves2half2(h0, h1);
                *(__half2*)(g_ql + base) = __halves2half2(l0, l1);
                *(__half2*)(g_qh + base + 8 * DH) = __halves2half2(h2, h3);
                *(__half2*)(g_ql + base + 8 * DH) = __halves2half2(l2, l3);
            }
        }
    } else if (sect == 1) {
        const int nc = n0 & 1023;
        #pragma unroll
        for (int mt = 0; mt < 4; mt++) {
            #pragma unroll
            for (int nt = 0; nt < 8; nt++) {
                const int c  = nc + warp_n * 64 + nt * 8 + tg * 2;
                const int hh = c >> 6, d = c & 63;
                const int r  = warp_m * 64 + mt * 16 + g;
                const size_t base = ((size_t)(bb * H_ + hh) * T_ + t0 + r) * DH + d;
                *(__half2*)(g_kh + base) =
                    __halves2half2(__float2half(acc[mt][nt][0]), __float2half(acc[mt][nt][1]));
                *(__half2*)(g_kh + base + 8 * DH) =
                    __halves2half2(__float2half(acc[mt][nt][2]), __float2half(acc[mt][nt][3]));
            }
        }
    } else {
        // V: transpose 128x128 tile through smem (stride 130: conflict-free)
        cp_wait0();
        __syncthreads();
        float* sf = (float*)smem_raw;
        #pragma unroll
        for (int mt = 0; mt < 4; mt++) {
            #pragma unroll
            for (int nt = 0; nt < 8; nt++) {
                const int r = warp_m * 64 + mt * 16 + g;
                const int c = warp_n * 64 + nt * 8 + tg * 2;
                sf[r * 130 + c]           = acc[mt][nt][0];
                sf[r * 130 + c + 1]       = acc[mt][nt][1];
                sf[(r + 8) * 130 + c]     = acc[mt][nt][2];
                sf[(r + 8) * 130 + c + 1] = acc[mt][nt][3];
            }
        }
        __syncthreads();
        const int dl = tid;            // column within tile (d), 0..127
        const int nv = (n0 - 2048) + dl;
        const int hh = nv >> 6, d = nv & 63;
        const size_t ob = ((size_t)(bb * H_ + hh) * DH + d) * T_ + t0;
        #pragma unroll 4
        for (int i = 0; i < 128; i += 2) {
            const float v0 = sf[i * 130 + dl];
            const float v1 = sf[(i + 1) * 130 + dl];
            *(__half2*)(g_vth + ob + i) =
                __halves2half2(__float2half(v0), __float2half(v1));
        }
    }
}

// proj GEMM: plain fp32 epilogue to d_out
__global__ __launch_bounds__(128, 2)
void proj_gemm_tc(float* __restrict__ out)
{
    extern __shared__ __align__(128) char smem_raw[];
    const uint32_t smem = smem_u32(smem_raw);
    const int m0 = blockIdx.y * 128;
    const int n0 = blockIdx.x * 128;

    float acc[4][8][4];
    gemm_mainloop(g_yhi, g_ylo, g_wph, m0, n0, smem, acc);

    const int lane = threadIdx.x & 31;
    const int warp = threadIdx.x >> 5;
    const int warp_m = warp & 1;
    const int warp_n = warp >> 1;
    const int g  = lane >> 2;
    const int tg = lane & 3;
    #pragma unroll
    for (int mt = 0; mt < 4; mt++) {
        #pragma unroll
        for (int nt = 0; nt < 8; nt++) {
            const int row = m0 + warp_m * 64 + mt * 16 + g;
            const int col = n0 + warp_n * 64 + nt * 8 + tg * 2;
            *(float2*)(out + (size_t)row * C_ + col) =
                make_float2(acc[mt][nt][0], acc[mt][nt][1]);
            *(float2*)(out + (size_t)(row + 8) * C_ + col) =
                make_float2(acc[mt][nt][2], acc[mt][nt][3]);
        }
    }
}

// ---------------------------------------------------------------------------
// fp16x2 HMMA flash attention (round-9 version, unchanged): CTA = 128 queries
// x one (b,h), 8 warps. QK: Q hi/lo x K single. PV: P hi/lo x V single.
// 3-buffer cp.async pipeline over K/V tiles of 64 keys.
// smem: Q hi/lo 32KB + 3 stages x 16KB = 80KB. 2 CTAs/SM.
// ---------------------------------------------------------------------------
#define ATT_STAGE 16384
#define ATT_SMEM  (32768 + 3 * ATT_STAGE)

__global__ __launch_bounds__(256, 2)
void attn_hmma_kernel()
{
    extern __shared__ __align__(128) char smem_raw[];
    const uint32_t smem = smem_u32(smem_raw);
    const uint32_t qsm  = smem;
    const uint32_t st0  = smem + 32768;

    const int tid  = threadIdx.x;
    const int lane = tid & 31;
    const int warp = tid >> 5;                       // 0..7
    const int qt   = (gridDim.x - 1) - blockIdx.x;   // heavy first
    const int bh   = blockIdx.z * H_ + blockIdx.y;
    const size_t qkb = (size_t)bh * T_ * DH;
    const size_t vb  = (size_t)bh * DH * T_;
    const int nkt = 2 * (qt + 1);

    // Q tile load (once; hi then lo)
    {
        const __half* s0 = g_qh + qkb + (size_t)qt * 128 * DH;
        const __half* s1 = g_ql + qkb + (size_t)qt * 128 * DH;
        #pragma unroll
        for (int t = 0; t < 8; t++) {
            const int rem = ((t & 3) << 8) + tid;    // 0..1023
            const int row = rem >> 3, ch = tid & 7;
            const __half* g = ((t >> 2) ? s1 : s0) + (size_t)row * DH + ch * 8;
            cp16(qsm + (t >> 2) * 16384 + row * 128 + ((ch ^ (row & 7)) << 4), g);
        }
    }
    auto load_kv = [&](int kt, uint32_t stage) {
        #pragma unroll
        for (int t = 0; t < 4; t++) {
            const int mat = t >> 1;                  // 0=Kh, 1=Vth
            const int rem = ((t & 1) << 8) + tid;    // 0..511
            const int row = rem >> 3, ch = tid & 7;
            const __half* g = (mat == 0)
                ? g_kh  + qkb + (size_t)(kt * 64 + row) * DH + ch * 8
                : g_vth + vb  + (size_t)row * T_ + kt * 64 + ch * 8;
            cp16(stage + mat * 8192 + row * 128 + ((ch ^ (row & 7)) << 4), g);
        }
    };

    load_kv(0, st0);
    cp_commit();                 // group: Q + kv0
    load_kv(1, st0 + ATT_STAGE);
    cp_commit();                 // group: kv1

    const int g   = lane >> 2;
    const int c2  = (lane & 3) * 2;
    const int q0w = qt * 128 + warp * 16;
    const int bkh = (lane >> 3) & 1;
    const int ah_ = lane >> 4;
    const int brow_base = ((lane >> 4) << 3) + (lane & 7);

    float O[8][4];
    #pragma unroll
    for (int nt = 0; nt < 8; nt++)
        #pragma unroll
        for (int i = 0; i < 4; i++) O[nt][i] = 0.f;
    float mrun0 = -1e30f, mrun1 = -1e30f;
    float lrun0 = 0.f, lrun1 = 0.f;

    for (int kt = 0; kt < nkt; kt++) {
        cp_wait1();
        __syncthreads();

        // prefetch kt+2 into the buffer freed by the barrier
        const uint32_t nb = st0 + ((kt + 2) % 3) * ATT_STAGE;
        if (kt + 2 < nkt) load_kv(kt + 2, nb);
        else              cp16(nb + tid * 16, g_kh + tid * 8);   // real dummy
        cp_commit();

        const uint32_t sb = st0 + (kt % 3) * ATT_STAGE;

        float sacc[8][4];
        #pragma unroll
        for (int nt = 0; nt < 8; nt++)
            #pragma unroll
            for (int i = 0; i < 4; i++) sacc[nt][i] = 0.f;

        // ---- S = Q K^T (fp16x2) ----
        #pragma unroll
        for (int kk = 0; kk < 4; kk++) {
            uint32_t qhf[4], qlf[4];
            {
                const int r = warp * 16 + (lane & 15);
                const uint32_t off = r * 128 + ((((kk << 1) | ah_) ^ (r & 7)) << 4);
                LDSM4(qhf, qsm + off);
                LDSM4(qlf, qsm + 16384 + off);
            }
            uint32_t khf[8][2];
            #pragma unroll
            for (int np = 0; np < 4; np++) {
                const int r = np * 16 + brow_base;
                const uint32_t off = r * 128 + ((((kk << 1) | bkh) ^ (r & 7)) << 4);
                uint32_t q4[4];
                LDSM4(q4, sb + off);
                khf[np * 2 + 0][0] = q4[0];  khf[np * 2 + 0][1] = q4[1];
                khf[np * 2 + 1][0] = q4[2];  khf[np * 2 + 1][1] = q4[3];
            }
            #pragma unroll
            for (int nt = 0; nt < 8; nt++) {
                mma16816(sacc[nt], qhf, khf[nt]);
                mma16816(sacc[nt], qlf, khf[nt]);
            }
        }

        // ---- causal mask (diagonal tiles only) ----
        if (kt >= 2 * qt) {
            const int kt64 = kt * 64;
            const int qr0 = q0w + g;
            #pragma unroll
            for (int nt = 0; nt < 8; nt++) {
                const int kc = kt64 + nt * 8 + c2;
                if (kc > qr0)         sacc[nt][0] = -1e30f;
                if (kc + 1 > qr0)     sacc[nt][1] = -1e30f;
                if (kc > qr0 + 8)     sacc[nt][2] = -1e30f;
                if (kc + 1 > qr0 + 8) sacc[nt][3] = -1e30f;
            }
        }

        // ---- online softmax ----
        {
            float h0 = -1e30f, h1 = -1e30f;
            #pragma unroll
            for (int nt = 0; nt < 8; nt++) {
                h0 = fmaxf(h0, fmaxf(sacc[nt][0], sacc[nt][1]));
                h1 = fmaxf(h1, fmaxf(sacc[nt][2], sacc[nt][3]));
            }
            h0 = fmaxf(h0, __shfl_xor_sync(0xffffffffu, h0, 1));
            h0 = fmaxf(h0, __shfl_xor_sync(0xffffffffu, h0, 2));
            h1 = fmaxf(h1, __shfl_xor_sync(0xffffffffu, h1, 1));
            h1 = fmaxf(h1, __shfl_xor_sync(0xffffffffu, h1, 2));
            const float m0 = fmaxf(mrun0, h0);
            const float m1 = fmaxf(mrun1, h1);
            const float a0 = __expf(mrun0 - m0);
            const float a1 = __expf(mrun1 - m1);
            mrun0 = m0;  mrun1 = m1;

            float s0 = 0.f, s1 = 0.f;
            #pragma unroll
            for (int nt = 0; nt < 8; nt++) {
                float p0 = __expf(sacc[nt][0] - m0);
                float p1 = __expf(sacc[nt][1] - m0);
                float p2 = __expf(sacc[nt][2] - m1);
                float p3 = __expf(sacc[nt][3] - m1);
                sacc[nt][0] = p0;  sacc[nt][1] = p1;
                sacc[nt][2] = p2;  sacc[nt][3] = p3;
                s0 += p0 + p1;
                s1 += p2 + p3;
            }
            s0 += __shfl_xor_sync(0xffffffffu, s0, 1);
            s0 += __shfl_xor_sync(0xffffffffu, s0, 2);
            s1 += __shfl_xor_sync(0xffffffffu, s1, 1);
            s1 += __shfl_xor_sync(0xffffffffu, s1, 2);
            lrun0 = lrun0 * a0 + s0;
            lrun1 = lrun1 * a1 + s1;

            #pragma unroll
            for (int nt = 0; nt < 8; nt++) {
                O[nt][0] *= a0;
                O[nt][1] *= a0;
                O[nt][2] *= a1;
                O[nt][3] *= a1;
            }
        }

        // ---- O += P V (fp16x2, P hi/lo in registers) ----
        #pragma unroll
        for (int kc = 0; kc < 4; kc++) {
            uint32_t ph[4], pl[4];
            #pragma unroll
            for (int half = 0; half < 2; half++) {
                const int nt = 2 * kc + half;
                float p0 = sacc[nt][0], p1 = sacc[nt][1];
                float p2 = sacc[nt][2], p3 = sacc[nt][3];
                float h0 = __half2float(__float2half(p0));
                float h1 = __half2float(__float2half(p1));
                float h2 = __half2float(__float2half(p2));
                float h3 = __half2float(__float2half(p3));
                ph[half * 2 + 0] = pack_f16x2(h0, h1);
                ph[half * 2 + 1] = pack_f16x2(h2, h3);
                pl[half * 2 + 0] = pack_f16x2(p0 - h0, p1 - h1);
                pl[half * 2 + 1] = pack_f16x2(p2 - h2, p3 - h3);
            }
            uint32_t vh[8][2];
            #pragma unroll
            for (int np = 0; np < 4; np++) {
                const int r = np * 16 + brow_base;
                const uint32_t off = r * 128 + ((((kc << 1) | bkh) ^ (r & 7)) << 4);
                uint32_t q4[4];
                LDSM4(q4, sb + 8192 + off);
                vh[np * 2 + 0][0] = q4[0];  vh[np * 2 + 0][1] = q4[1];
                vh[np * 2 + 1][0] = q4[2];  vh[np * 2 + 1][1] = q4[3];
            }
            #pragma unroll
            for (int nt = 0; nt < 8; nt++) {
                mma16816(O[nt], ph, vh[nt]);
                mma16816(O[nt], pl, vh[nt]);
            }
        }
    }

    // ---- epilogue: y = O / l, written as fp16 hi/lo for the proj GEMM ----
    const int hcol = blockIdx.y * 64;
    const float inv0 = 1.f / lrun0;
    const float inv1 = 1.f / lrun1;
    const int r0 = blockIdx.z * T_ + q0w + g;
    #pragma unroll
    for (int nt = 0; nt < 8; nt++) {
        const size_t o0 = (size_t)r0 * C_ + hcol + nt * 8 + c2;
        const size_t o1 = o0 + (size_t)8 * C_;
        __half h0, h1, h2, h3, l0, l1, l2, l3;
        split2h(O[nt][0] * inv0, h0, l0);
        split2h(O[nt][1] * inv0, h1, l1);
        split2h(O[nt][2] * inv1, h2, l2);
        split2h(O[nt][3] * inv1, h3, l3);
        *(__half2*)(g_yhi + o0) = __halves2half2(h0, h1);
        *(__half2*)(g_ylo + o0) = __halves2half2(l0, l1);
        *(__half2*)(g_yhi + o1) = __halves2half2(h2, h3);
        *(__half2*)(g_ylo + o1) = __halves2half2(l2, l3);
    }
}

// ---------------------------------------------------------------------------
extern "C" void kernel_launch(void* const* d_in, const int* in_sizes, int n_in,
                              void* d_out, int out_size)
{
    const float* x      = (const float*)d_in[0];
    const float* w_attn = (const float*)d_in[1];
    const float* w_proj = (const float*)d_in[2];
    float* out = (float*)d_out;

    static bool attr_done = false;
    if (!attr_done) {
        cudaFuncSetAttribute(qkv_gemm_tc,  cudaFuncAttributeMaxDynamicSharedMemorySize, GEMM_SMEM);
        cudaFuncSetAttribute(proj_gemm_tc, cudaFuncAttributeMaxDynamicSharedMemorySize, GEMM_SMEM);
        cudaFuncSetAttribute(attn_hmma_kernel, cudaFuncAttributeMaxDynamicSharedMemorySize, ATT_SMEM);
        attr_done = true;
    }

    __half *xhi, *xlo, *wah, *wph;
    cudaGetSymbolAddress((void**)&xhi, g_xhi);
    cudaGetSymbolAddress((void**)&xlo, g_xlo);
    cudaGetSymbolAddress((void**)&wah, g_wah);
    cudaGetSymbolAddress((void**)&wph, g_wph);

    // 1) split x -> fp16 hi/lo
    split_kernel<<<(M_ * KD) / 1024, 256>>>(x, xhi, xlo, M_ * KD);
    // 2) transpose+convert weights to single fp16
    {
        dim3 grid(KD / 32, (3 * C_) / 32);
        convT_kernel<<<grid, dim3(32, 8)>>>(w_attn, wah, KD, 3 * C_);
    }
    {
        dim3 grid(KD / 32, C_ / 32);
        convT_kernel<<<grid, dim3(32, 8)>>>(w_proj, wph, KD, C_);
    }
    // 3) QKV GEMM (HMMA fp16x2, 4-warp CTAs, warp tile 64x64)
    {
        dim3 grid((3 * C_) / 128, M_ / 128);
        qkv_gemm_tc<<<grid, 128, GEMM_SMEM>>>();
    }
    // 4) HMMA flash attention (fp16x2, 8 warps) -> g_yhi/g_ylo
    {
        dim3 grid(T_ / 128, H_, B_);
        attn_hmma_kernel<<<grid, 256, ATT_SMEM>>>();
    }
    // 5) proj GEMM (HMMA fp16x2, 4-warp CTAs) -> out
    {
        dim3 grid(C_ / 128, M_ / 128);
        proj_gemm_tc<<<grid, 128, GEMM_SMEM>>>(out);
    }
}

// round 11
// speedup vs baseline: 1.6593x; 1.1844x over previous
#include <cuda_runtime.h>
#include <cuda_fp16.h>
#include <cstdint>

#define B_  2
#define T_  2048
#define C_  1024
#define H_  16
#define DH  64
#define M_  (B_ * T_)
#define KD  1024

// ---------------- scratch (static device globals) ----------------
__device__ __half g_xhi[(size_t)M_ * KD];
__device__ __half g_xlo[(size_t)M_ * KD];
__device__ __half g_wah[(size_t)3 * C_ * KD];    // W_attn^T [3072,1024] single fp16
__device__ __half g_wph[(size_t)C_ * KD];        // W_proj^T [1024,1024] single fp16
__device__ __half g_yh [(size_t)M_ * KD];        // attention out (single fp16)
// head-major attention operands (written by fused QKV epilogue)
__device__ __half g_qh[(size_t)B_ * H_ * T_ * DH];
__device__ __half g_ql[(size_t)B_ * H_ * T_ * DH];
__device__ __half g_kh[(size_t)B_ * H_ * T_ * DH];          // K single fp16
__device__ __half g_vth[(size_t)B_ * H_ * DH * T_];         // V^T single fp16 [bh][d][t]

// ---------------- base-ISA PTX helpers (sm_80+) ----------------
__device__ __forceinline__ uint32_t smem_u32(const void* p) {
    uint32_t a;
    asm("{ .reg .u64 t; cvta.to.shared.u64 t, %1; cvt.u32.u64 %0, t; }" : "=r"(a) : "l"(p));
    return a;
}
__device__ __forceinline__ void cp16(uint32_t s, const void* g) {
    asm volatile("cp.async.cg.shared.global [%0], [%1], 16;" :: "r"(s), "l"(g));
}
__device__ __forceinline__ void cp_commit() {
    asm volatile("cp.async.commit_group;" ::: "memory");
}
__device__ __forceinline__ void cp_wait1() {
    asm volatile("cp.async.wait_group 1;" ::: "memory");
}
__device__ __forceinline__ void cp_wait0() {
    asm volatile("cp.async.wait_group 0;" ::: "memory");
}
#define LDSM4(R, addr) \
    asm volatile("ldmatrix.sync.aligned.m8n8.x4.shared.b16 {%0,%1,%2,%3}, [%4];" \
                 : "=r"((R)[0]), "=r"((R)[1]), "=r"((R)[2]), "=r"((R)[3]) : "r"(addr))

__device__ __forceinline__ void mma16816(float* c, const uint32_t* a, const uint32_t* b) {
    asm volatile(
        "mma.sync.aligned.m16n8k16.row.col.f32.f16.f16.f32 "
        "{%0,%1,%2,%3}, {%4,%5,%6,%7}, {%8,%9}, {%0,%1,%2,%3};"
        : "+f"(c[0]), "+f"(c[1]), "+f"(c[2]), "+f"(c[3])
        : "r"(a[0]), "r"(a[1]), "r"(a[2]), "r"(a[3]), "r"(b[0]), "r"(b[1]));
}
// pack two fp32 -> f16x2 reg, lo in low half
__device__ __forceinline__ uint32_t pack_f16x2(float lo, float hi) {
    uint32_t d;
    asm("cvt.rn.f16x2.f32 %0, %1, %2;" : "=r"(d) : "f"(hi), "f"(lo));
    return d;
}

// ---------------- fp32 -> fp16 hi/lo split ----------------
__device__ __forceinline__ void split2h(float v, __half& h, __half& l) {
    h = __float2half(v);
    l = __float2half(v - __half2float(h));
}

__global__ __launch_bounds__(256)
void split_kernel(const float* __restrict__ in,
                  __half* __restrict__ hi, __half* __restrict__ lo, int n)
{
    int i = (blockIdx.x * 256 + threadIdx.x) * 4;
    if (i >= n) return;
    float4 v = *(const float4*)(in + i);
    __half h0, h1, h2, h3, l0, l1, l2, l3;
    split2h(v.x, h0, l0); split2h(v.y, h1, l1);
    split2h(v.z, h2, l2); split2h(v.w, h3, l3);
    *(__half2*)(hi + i)     = __halves2half2(h0, h1);
    *(__half2*)(hi + i + 2) = __halves2half2(h2, h3);
    *(__half2*)(lo + i)     = __halves2half2(l0, l1);
    *(__half2*)(lo + i + 2) = __halves2half2(l2, l3);
}

// transpose + convert: W fp32 [Kdim, Ndim] -> W^T single fp16 [Ndim, Kdim]
__global__ __launch_bounds__(256)
void convT_kernel(const float* __restrict__ W, __half* __restrict__ WT,
                  int Kdim, int Ndim)
{
    __shared__ float tile[32][33];
    const int k0 = blockIdx.x * 32, n0 = blockIdx.y * 32;
    const int tx = threadIdx.x, ty = threadIdx.y;   // 32 x 8
    #pragma unroll
    for (int i = 0; i < 32; i += 8)
        tile[ty + i][tx] = W[(size_t)(k0 + ty + i) * Ndim + n0 + tx];
    __syncthreads();
    #pragma unroll
    for (int i = 0; i < 32; i += 8) {
        WT[(size_t)(n0 + ty + i) * Kdim + k0 + tx] = __float2half(tile[tx][ty + i]);
    }
}

// ---------------------------------------------------------------------------
// fp16 HMMA GEMM mainloop, templated on A-split:
//   SPLIT_A=true:  C = (Ahi+Alo) * Bh^T   (2 MMAs per fragment pair)
//   SPLIT_A=false: C =  Ahi      * Bh^T   (1 MMA; Alo never loaded)
// CTA 128x128, 4 warps 2(M) x 2(N), warp tile 64x64, BK=64,
// 2-stage cp.async pipeline. Stage: Ahi 16K | Alo 16K | Bh 16K = 48KB.
// ---------------------------------------------------------------------------
#define MAT_BYTES   16384
#define STAGE_BYTES (3 * MAT_BYTES)
#define GEMM_SMEM   (2 * STAGE_BYTES)
#define NSTAGE      (KD / 64)

template<bool SPLIT_A>
__device__ __forceinline__ void gemm_mainloop(
    const __half* __restrict__ Ahi, const __half* __restrict__ Alo,
    const __half* __restrict__ Bh,
    int m0, int n0, uint32_t smem, float (&acc)[4][8][4])
{
    const int tid    = threadIdx.x;      // 0..127
    const int lane   = tid & 31;
    const int warp   = tid >> 5;         // 0..3
    const int warp_m = warp & 1;
    const int warp_n = warp >> 1;        // 0..1

    auto load_stage = [&](int kofs, uint32_t stage_u32) {
        constexpr int NMAT = SPLIT_A ? 3 : 2;
        #pragma unroll
        for (int t = 0; t < 8 * NMAT; t++) {
            const int mi  = t >> 3;                   // 0..NMAT-1 (compile-time)
            const int rem = ((t & 7) << 7) + tid;     // 0..1023
            const int row = rem >> 3;
            const int ch  = tid & 7;
            const __half* g;
            int slot;
            if (SPLIT_A) {
                g = (mi == 0 ? Ahi : (mi == 1 ? Alo : Bh))
                    + (size_t)((mi == 2 ? n0 : m0) + row) * KD + kofs + ch * 8;
                slot = mi;
            } else {
                g = (mi == 0 ? Ahi : Bh)
                    + (size_t)((mi == 1 ? n0 : m0) + row) * KD + kofs + ch * 8;
                slot = (mi == 0) ? 0 : 2;             // keep B at 2*MAT_BYTES
            }
            uint32_t s = stage_u32 + slot * MAT_BYTES + row * 128
                       + ((ch ^ (row & 7)) << 4);
            cp16(s, g);
        }
    };

    #pragma unroll
    for (int i = 0; i < 4; i++)
        #pragma unroll
        for (int j = 0; j < 8; j++)
            #pragma unroll
            for (int k = 0; k < 4; k++) acc[i][j][k] = 0.f;

    load_stage(0, smem);
    cp_commit();
    load_stage(64, smem + STAGE_BYTES);
    cp_commit();
    cp_wait1();
    __syncthreads();

    const int arow = warp_m * 64 + (lane & 15);
    const int ah_  = lane >> 4;
    const int brow = warp_n * 64 + ((lane >> 4) << 3) + (lane & 7);
    const int bkh  = (lane >> 3) & 1;

    for (int ks = 0; ks < NSTAGE; ks++) {
        const uint32_t sb = smem + (ks & 1) * STAGE_BYTES;

        #pragma unroll
        for (int kk = 0; kk < 4; kk++) {
            uint32_t ahf[4][4], alf[4][4], bhf[8][2];
            #pragma unroll
            for (int mt = 0; mt < 4; mt++) {
                const int r = arow + mt * 16;
                const uint32_t off = r * 128 + ((((kk << 1) | ah_) ^ (r & 7)) << 4);
                LDSM4(ahf[mt], sb + off);
                if (SPLIT_A) LDSM4(alf[mt], sb + MAT_BYTES + off);
            }
            #pragma unroll
            for (int np = 0; np < 4; np++) {
                const int r = brow + np * 16;
                const uint32_t off = r * 128 + ((((kk << 1) | bkh) ^ (r & 7)) << 4);
                uint32_t q[4];
                LDSM4(q, sb + 2 * MAT_BYTES + off);
                bhf[np * 2 + 0][0] = q[0];  bhf[np * 2 + 0][1] = q[1];
                bhf[np * 2 + 1][0] = q[2];  bhf[np * 2 + 1][1] = q[3];
            }
            #pragma unroll
            for (int mt = 0; mt < 4; mt++)
                #pragma unroll
                for (int nt = 0; nt < 8; nt++) {
                    mma16816(acc[mt][nt], ahf[mt], bhf[nt]);
                    if (SPLIT_A) mma16816(acc[mt][nt], alf[mt], bhf[nt]);
                }
        }

        __syncthreads();
        if (ks + 2 < NSTAGE)
            load_stage((ks + 2) * 64, sb);
        cp_commit();
        cp_wait1();
        __syncthreads();
    }
}

// QKV GEMM with fused epilogue: Q (split-A) -> hi/lo fp16 (scaled 0.125),
// K (single-A) -> single fp16 head-major, V (single-A) -> transposed fp16.
__global__ __launch_bounds__(128, 2)
void qkv_gemm_tc()
{
    extern __shared__ __align__(128) char smem_raw[];
    const uint32_t smem = smem_u32(smem_raw);
    const int m0 = blockIdx.y * 128;
    const int n0 = blockIdx.x * 128;
    const int sect = n0 >> 10;       // 0=Q, 1=K, 2=V

    float acc[4][8][4];
    if (sect == 0) gemm_mainloop<true >(g_xhi, g_xlo, g_wah, m0, n0, smem, acc);
    else           gemm_mainloop<false>(g_xhi, g_xlo, g_wah, m0, n0, smem, acc);

    const int tid  = threadIdx.x;
    const int lane = tid & 31;
    const int warp = tid >> 5;
    const int warp_m = warp & 1;
    const int warp_n = warp >> 1;
    const int g  = lane >> 2;
    const int tg = lane & 3;
    const int bb = m0 >> 11;
    const int t0 = m0 & 2047;

    if (sect == 0) {
        const int nc = n0 & 1023;
        #pragma unroll
        for (int mt = 0; mt < 4; mt++) {
            #pragma unroll
            for (int nt = 0; nt < 8; nt++) {
                const int c  = nc + warp_n * 64 + nt * 8 + tg * 2;
                const int hh = c >> 6, d = c & 63;
                const int r  = warp_m * 64 + mt * 16 + g;
                const size_t base = ((size_t)(bb * H_ + hh) * T_ + t0 + r) * DH + d;
                __half h0, h1, h2, h3, l0, l1, l2, l3;
                split2h(acc[mt][nt][0] * 0.125f, h0, l0);
                split2h(acc[mt][nt][1] * 0.125f, h1, l1);
                split2h(acc[mt][nt][2] * 0.125f, h2, l2);
                split2h(acc[mt][nt][3] * 0.125f, h3, l3);
                *(__half2*)(g_qh + base) = __halves2half2(h0, h1);
                *(__half2*)(g_ql + base) = __halves2half2(l0, l1);
                *(__half2*)(g_qh + base + 8 * DH) = __halves2half2(h2, h3);
                *(__half2*)(g_ql + base + 8 * DH) = __halves2half2(l2, l3);
            }
        }
    } else if (sect == 1) {
        const int nc = n0 & 1023;
        #pragma unroll
        for (int mt = 0; mt < 4; mt++) {
            #pragma unroll
            for (int nt = 0; nt < 8; nt++) {
                const int c  = nc + warp_n * 64 + nt * 8 + tg * 2;
                const int hh = c >> 6, d = c & 63;
                const int r  = warp_m * 64 + mt * 16 + g;
                const size_t base = ((size_t)(bb * H_ + hh) * T_ + t0 + r) * DH + d;
                *(__half2*)(g_kh + base) =
                    __halves2half2(__float2half(acc[mt][nt][0]), __float2half(acc[mt][nt][1]));
                *(__half2*)(g_kh + base + 8 * DH) =
                    __halves2half2(__float2half(acc[mt][nt][2]), __float2half(acc[mt][nt][3]));
            }
        }
    } else {
        // V: transpose 128x128 tile through smem (stride 130: conflict-free)
        cp_wait0();
        __syncthreads();
        float* sf = (float*)smem_raw;
        #pragma unroll
        for (int mt = 0; mt < 4; mt++) {
            #pragma unroll
            for (int nt = 0; nt < 8; nt++) {
                const int r = warp_m * 64 + mt * 16 + g;
                const int c = warp_n * 64 + nt * 8 + tg * 2;
                sf[r * 130 + c]           = acc[mt][nt][0];
                sf[r * 130 + c + 1]       = acc[mt][nt][1];
                sf[(r + 8) * 130 + c]     = acc[mt][nt][2];
                sf[(r + 8) * 130 + c + 1] = acc[mt][nt][3];
            }
        }
        __syncthreads();
        const int dl = tid;            // column within tile (d), 0..127
        const int nv = (n0 - 2048) + dl;
        const int hh = nv >> 6, d = nv & 63;
        const size_t ob = ((size_t)(bb * H_ + hh) * DH + d) * T_ + t0;
        #pragma unroll 4
        for (int i = 0; i < 128; i += 2) {
            const float v0 = sf[i * 130 + dl];
            const float v1 = sf[(i + 1) * 130 + dl];
            *(__half2*)(g_vth + ob + i) =
                __halves2half2(__float2half(v0), __float2half(v1));
        }
    }
}

// proj GEMM: single-A (y fp16), plain fp32 epilogue to d_out
__global__ __launch_bounds__(128, 2)
void proj_gemm_tc(float* __restrict__ out)
{
    extern __shared__ __align__(128) char smem_raw[];
    const uint32_t smem = smem_u32(smem_raw);
    const int m0 = blockIdx.y * 128;
    const int n0 = blockIdx.x * 128;

    float acc[4][8][4];
    gemm_mainloop<false>(g_yh, g_yh, g_wph, m0, n0, smem, acc);

    const int lane = threadIdx.x & 31;
    const int warp = threadIdx.x >> 5;
    const int warp_m = warp & 1;
    const int warp_n = warp >> 1;
    const int g  = lane >> 2;
    const int tg = lane & 3;
    #pragma unroll
    for (int mt = 0; mt < 4; mt++) {
        #pragma unroll
        for (int nt = 0; nt < 8; nt++) {
            const int row = m0 + warp_m * 64 + mt * 16 + g;
            const int col = n0 + warp_n * 64 + nt * 8 + tg * 2;
            *(float2*)(out + (size_t)row * C_ + col) =
                make_float2(acc[mt][nt][0], acc[mt][nt][1]);
            *(float2*)(out + (size_t)(row + 8) * C_ + col) =
                make_float2(acc[mt][nt][2], acc[mt][nt][3]);
        }
    }
}

// ---------------------------------------------------------------------------
// fp16x2 HMMA flash attention: CTA = 128 queries x one (b,h), 8 warps.
// QK: Q hi/lo x K single. PV: P hi/lo x V single.
// 3-buffer cp.async pipeline over K/V tiles of 64 keys.
// Epilogue writes y as SINGLE fp16 (proj is single-A now).
// smem: Q hi/lo 32KB + 3 stages x 16KB = 80KB. 2 CTAs/SM.
// ---------------------------------------------------------------------------
#define ATT_STAGE 16384
#define ATT_SMEM  (32768 + 3 * ATT_STAGE)

__global__ __launch_bounds__(256, 2)
void attn_hmma_kernel()
{
    extern __shared__ __align__(128) char smem_raw[];
    const uint32_t smem = smem_u32(smem_raw);
    const uint32_t qsm  = smem;
    const uint32_t st0  = smem + 32768;

    const int tid  = threadIdx.x;
    const int lane = tid & 31;
    const int warp = tid >> 5;                       // 0..7
    const int qt   = (gridDim.x - 1) - blockIdx.x;   // heavy first
    const int bh   = blockIdx.z * H_ + blockIdx.y;
    const size_t qkb = (size_t)bh * T_ * DH;
    const size_t vb  = (size_t)bh * DH * T_;
    const int nkt = 2 * (qt + 1);

    // Q tile load (once; hi then lo)
    {
        const __half* s0 = g_qh + qkb + (size_t)qt * 128 * DH;
        const __half* s1 = g_ql + qkb + (size_t)qt * 128 * DH;
        #pragma unroll
        for (int t = 0; t < 8; t++) {
            const int rem = ((t & 3) << 8) + tid;    // 0..1023
            const int row = rem >> 3, ch = tid & 7;
            const __half* g = ((t >> 2) ? s1 : s0) + (size_t)row * DH + ch * 8;
            cp16(qsm + (t >> 2) * 16384 + row * 128 + ((ch ^ (row & 7)) << 4), g);
        }
    }
    auto load_kv = [&](int kt, uint32_t stage) {
        #pragma unroll
        for (int t = 0; t < 4; t++) {
            const int mat = t >> 1;                  // 0=Kh, 1=Vth
            const int rem = ((t & 1) << 8) + tid;    // 0..511
            const int row = rem >> 3, ch = tid & 7;
            const __half* g = (mat == 0)
                ? g_kh  + qkb + (size_t)(kt * 64 + row) * DH + ch * 8
                : g_vth + vb  + (size_t)row * T_ + kt * 64 + ch * 8;
            cp16(stage + mat * 8192 + row * 128 + ((ch ^ (row & 7)) << 4), g);
        }
    };

    load_kv(0, st0);
    cp_commit();                 // group: Q + kv0
    load_kv(1, st0 + ATT_STAGE);
    cp_commit();                 // group: kv1

    const int g   = lane >> 2;
    const int c2  = (lane & 3) * 2;
    const int q0w = qt * 128 + warp * 16;
    const int bkh = (lane >> 3) & 1;
    const int ah_ = lane >> 4;
    const int brow_base = ((lane >> 4) << 3) + (lane & 7);

    float O[8][4];
    #pragma unroll
    for (int nt = 0; nt < 8; nt++)
        #pragma unroll
        for (int i = 0; i < 4; i++) O[nt][i] = 0.f;
    float mrun0 = -1e30f, mrun1 = -1e30f;
    float lrun0 = 0.f, lrun1 = 0.f;

    for (int kt = 0; kt < nkt; kt++) {
        cp_wait1();
        __syncthreads();

        // prefetch kt+2 into the buffer freed by the barrier
        const uint32_t nb = st0 + ((kt + 2) % 3) * ATT_STAGE;
        if (kt + 2 < nkt) load_kv(kt + 2, nb);
        else              cp16(nb + tid * 16, g_kh + tid * 8);   // real dummy
        cp_commit();

        const uint32_t sb = st0 + (kt % 3) * ATT_STAGE;

        float sacc[8][4];
        #pragma unroll
        for (int nt = 0; nt < 8; nt++)
            #pragma unroll
            for (int i = 0; i < 4; i++) sacc[nt][i] = 0.f;

        // ---- S = Q K^T (fp16x2) ----
        #pragma unroll
        for (int kk = 0; kk < 4; kk++) {
            uint32_t qhf[4], qlf[4];
            {
                const int r = warp * 16 + (lane & 15);
                const uint32_t off = r * 128 + ((((kk << 1) | ah_) ^ (r & 7)) << 4);
                LDSM4(qhf, qsm + off);
                LDSM4(qlf, qsm + 16384 + off);
            }
            uint32_t khf[8][2];
            #pragma unroll
            for (int np = 0; np < 4; np++) {
                const int r = np * 16 + brow_base;
                const uint32_t off = r * 128 + ((((kk << 1) | bkh) ^ (r & 7)) << 4);
                uint32_t q4[4];
                LDSM4(q4, sb + off);
                khf[np * 2 + 0][0] = q4[0];  khf[np * 2 + 0][1] = q4[1];
                khf[np * 2 + 1][0] = q4[2];  khf[np * 2 + 1][1] = q4[3];
            }
            #pragma unroll
            for (int nt = 0; nt < 8; nt++) {
                mma16816(sacc[nt], qhf, khf[nt]);
                mma16816(sacc[nt], qlf, khf[nt]);
            }
        }

        // ---- causal mask (diagonal tiles only) ----
        if (kt >= 2 * qt) {
            const int kt64 = kt * 64;
            const int qr0 = q0w + g;
            #pragma unroll
            for (int nt = 0; nt < 8; nt++) {
                const int kc = kt64 + nt * 8 + c2;
                if (kc > qr0)         sacc[nt][0] = -1e30f;
                if (kc + 1 > qr0)     sacc[nt][1] = -1e30f;
                if (kc > qr0 + 8)     sacc[nt][2] = -1e30f;
                if (kc + 1 > qr0 + 8) sacc[nt][3] = -1e30f;
            }
        }

        // ---- online softmax ----
        {
            float h0 = -1e30f, h1 = -1e30f;
            #pragma unroll
            for (int nt = 0; nt < 8; nt++) {
                h0 = fmaxf(h0, fmaxf(sacc[nt][0], sacc[nt][1]));
                h1 = fmaxf(h1, fmaxf(sacc[nt][2], sacc[nt][3]));
            }
            h0 = fmaxf(h0, __shfl_xor_sync(0xffffffffu, h0, 1));
            h0 = fmaxf(h0, __shfl_xor_sync(0xffffffffu, h0, 2));
            h1 = fmaxf(h1, __shfl_xor_sync(0xffffffffu, h1, 1));
            h1 = fmaxf(h1, __shfl_xor_sync(0xffffffffu, h1, 2));
            const float m0 = fmaxf(mrun0, h0);
            const float m1 = fmaxf(mrun1, h1);
            const float a0 = __expf(mrun0 - m0);
            const float a1 = __expf(mrun1 - m1);
            mrun0 = m0;  mrun1 = m1;

            float s0 = 0.f, s1 = 0.f;
            #pragma unroll
            for (int nt = 0; nt < 8; nt++) {
                float p0 = __expf(sacc[nt][0] - m0);
                float p1 = __expf(sacc[nt][1] - m0);
                float p2 = __expf(sacc[nt][2] - m1);
                float p3 = __expf(sacc[nt][3] - m1);
                sacc[nt][0] = p0;  sacc[nt][1] = p1;
                sacc[nt][2] = p2;  sacc[nt][3] = p3;
                s0 += p0 + p1;
                s1 += p2 + p3;
            }
            s0 += __shfl_xor_sync(0xffffffffu, s0, 1);
            s0 += __shfl_xor_sync(0xffffffffu, s0, 2);
            s1 += __shfl_xor_sync(0xffffffffu, s1, 1);
            s1 += __shfl_xor_sync(0xffffffffu, s1, 2);
            lrun0 = lrun0 * a0 + s0;
            lrun1 = lrun1 * a1 + s1;

            #pragma unroll
            for (int nt = 0; nt < 8; nt++) {
                O[nt][0] *= a0;
                O[nt][1] *= a0;
                O[nt][2] *= a1;
                O[nt][3] *= a1;
            }
        }

        // ---- O += P V (fp16x2, P hi/lo in registers) ----
        #pragma unroll
        for (int kc = 0; kc < 4; kc++) {
            uint32_t ph[4], pl[4];
            #pragma unroll
            for (int half = 0; half < 2; half++) {
                const int nt = 2 * kc + half;
                float p0 = sacc[nt][0], p1 = sacc[nt][1];
                float p2 = sacc[nt][2], p3 = sacc[nt][3];
                float h0 = __half2float(__float2half(p0));
                float h1 = __half2float(__float2half(p1));
                float h2 = __half2float(__float2half(p2));
                float h3 = __half2float(__float2half(p3));
                ph[half * 2 + 0] = pack_f16x2(h0, h1);
                ph[half * 2 + 1] = pack_f16x2(h2, h3);
                pl[half * 2 + 0] = pack_f16x2(p0 - h0, p1 - h1);
                pl[half * 2 + 1] = pack_f16x2(p2 - h2, p3 - h3);
            }
            uint32_t vh[8][2];
            #pragma unroll
            for (int np = 0; np < 4; np++) {
                const int r = np * 16 + brow_base;
                const uint32_t off = r * 128 + ((((kc << 1) | bkh) ^ (r & 7)) << 4);
                uint32_t q4[4];
                LDSM4(q4, sb + 8192 + off);
                vh[np * 2 + 0][0] = q4[0];  vh[np * 2 + 0][1] = q4[1];
                vh[np * 2 + 1][0] = q4[2];  vh[np * 2 + 1][1] = q4[3];
            }
            #pragma unroll
            for (int nt = 0; nt < 8; nt++) {
                mma16816(O[nt], ph, vh[nt]);
                mma16816(O[nt], pl, vh[nt]);
            }
        }
    }

    // ---- epilogue: y = O / l, written as SINGLE fp16 for the proj GEMM ----
    const int hcol = blockIdx.y * 64;
    const float inv0 = 1.f / lrun0;
    const float inv1 = 1.f / lrun1;
    const int r0 = blockIdx.z * T_ + q0w + g;
    #pragma unroll
    for (int nt = 0; nt < 8; nt++) {
        const size_t o0 = (size_t)r0 * C_ + hcol + nt * 8 + c2;
        const size_t o1 = o0 + (size_t)8 * C_;
        *(__half2*)(g_yh + o0) = __halves2half2(
            __float2half(O[nt][0] * inv0), __float2half(O[nt][1] * inv0));
        *(__half2*)(g_yh + o1) = __halves2half2(
            __float2half(O[nt][2] * inv1), __float2half(O[nt][3] * inv1));
    }
}

// ---------------------------------------------------------------------------
extern "C" void kernel_launch(void* const* d_in, const int* in_sizes, int n_in,
                              void* d_out, int out_size)
{
    const float* x      = (const float*)d_in[0];
    const float* w_attn = (const float*)d_in[1];
    const float* w_proj = (const float*)d_in[2];
    float* out = (float*)d_out;

    static bool attr_done = false;
    if (!attr_done) {
        cudaFuncSetAttribute(qkv_gemm_tc,  cudaFuncAttributeMaxDynamicSharedMemorySize, GEMM_SMEM);
        cudaFuncSetAttribute(proj_gemm_tc, cudaFuncAttributeMaxDynamicSharedMemorySize, GEMM_SMEM);
        cudaFuncSetAttribute(attn_hmma_kernel, cudaFuncAttributeMaxDynamicSharedMemorySize, ATT_SMEM);
        attr_done = true;
    }

    __half *xhi, *xlo, *wah, *wph;
    cudaGetSymbolAddress((void**)&xhi, g_xhi);
    cudaGetSymbolAddress((void**)&xlo, g_xlo);
    cudaGetSymbolAddress((void**)&wah, g_wah);
    cudaGetSymbolAddress((void**)&wph, g_wph);

    // 1) split x -> fp16 hi/lo
    split_kernel<<<(M_ * KD) / 1024, 256>>>(x, xhi, xlo, M_ * KD);
    // 2) transpose+convert weights to single fp16
    {
        dim3 grid(KD / 32, (3 * C_) / 32);
        convT_kernel<<<grid, dim3(32, 8)>>>(w_attn, wah, KD, 3 * C_);
    }
    {
        dim3 grid(KD / 32, C_ / 32);
        convT_kernel<<<grid, dim3(32, 8)>>>(w_proj, wph, KD, C_);
    }
    // 3) QKV GEMM (Q split-A, K/V single-A) with fused head-major epilogue
    {
        dim3 grid((3 * C_) / 128, M_ / 128);
        qkv_gemm_tc<<<grid, 128, GEMM_SMEM>>>();
    }
    // 4) HMMA flash attention (fp16x2, 8 warps) -> g_yh (single fp16)
    {
        dim3 grid(T_ / 128, H_, B_);
        attn_hmma_kernel<<<grid, 256, ATT_SMEM>>>();
    }
    // 5) proj GEMM (single-A) -> out
    {
        dim3 grid(C_ / 128, M_ / 128);
        proj_gemm_tc<<<grid, 128, GEMM_SMEM>>>(out);
    }
}

// round 13
// speedup vs baseline: 2.3868x; 1.4384x over previous
#include <cuda_runtime.h>
#include <cuda_fp16.h>
#include <cstdint>

#define B_  2
#define T_  2048
#define C_  1024
#define H_  16
#define DH  64
#define M_  (B_ * T_)
#define KD  1024

// Q pre-scale: (1/sqrt(64)) * log2(e)  — softmax done in base 2
#define QSCALE 0.1803368801111204f

// ---------------- scratch (static device globals) ----------------
__device__ __half g_xh [(size_t)M_ * KD];        // x single fp16
__device__ __half g_wah[(size_t)3 * C_ * KD];    // W_attn^T [3072,1024] fp16
__device__ __half g_wph[(size_t)C_ * KD];        // W_proj^T [1024,1024] fp16
__device__ __half g_yh [(size_t)M_ * KD];        // attention out fp16
// head-major attention operands (written by fused QKV epilogue)
__device__ __half g_qh [(size_t)B_ * H_ * T_ * DH];   // Q (scaled by QSCALE)
__device__ __half g_kh [(size_t)B_ * H_ * T_ * DH];   // K
__device__ __half g_vth[(size_t)B_ * H_ * DH * T_];   // V^T [bh][d][t]

// ---------------- base-ISA PTX helpers (sm_80+) ----------------
__device__ __forceinline__ uint32_t smem_u32(const void* p) {
    uint32_t a;
    asm("{ .reg .u64 t; cvta.to.shared.u64 t, %1; cvt.u32.u64 %0, t; }" : "=r"(a) : "l"(p));
    return a;
}
__device__ __forceinline__ void cp16(uint32_t s, const void* g) {
    asm volatile("cp.async.cg.shared.global [%0], [%1], 16;" :: "r"(s), "l"(g));
}
__device__ __forceinline__ void cp_commit() {
    asm volatile("cp.async.commit_group;" ::: "memory");
}
__device__ __forceinline__ void cp_wait1() {
    asm volatile("cp.async.wait_group 1;" ::: "memory");
}
__device__ __forceinline__ void cp_wait0() {
    asm volatile("cp.async.wait_group 0;" ::: "memory");
}
#define LDSM4(R, addr) \
    asm volatile("ldmatrix.sync.aligned.m8n8.x4.shared.b16 {%0,%1,%2,%3}, [%4];" \
                 : "=r"((R)[0]), "=r"((R)[1]), "=r"((R)[2]), "=r"((R)[3]) : "r"(addr))

__device__ __forceinline__ void mma16816(float* c, const uint32_t* a, const uint32_t* b) {
    asm volatile(
        "mma.sync.aligned.m16n8k16.row.col.f32.f16.f16.f32 "
        "{%0,%1,%2,%3}, {%4,%5,%6,%7}, {%8,%9}, {%0,%1,%2,%3};"
        : "+f"(c[0]), "+f"(c[1]), "+f"(c[2]), "+f"(c[3])
        : "r"(a[0]), "r"(a[1]), "r"(a[2]), "r"(a[3]), "r"(b[0]), "r"(b[1]));
}
__device__ __forceinline__ uint32_t pack_f16x2(float lo, float hi) {
    uint32_t d;
    asm("cvt.rn.f16x2.f32 %0, %1, %2;" : "=r"(d) : "f"(hi), "f"(lo));
    return d;
}
__device__ __forceinline__ float ex2(float x) {
    float y;
    asm("ex2.approx.ftz.f32 %0, %1;" : "=f"(y) : "f"(x));
    return y;
}

// ---------------- prep kernels ----------------
// elementwise fp32 -> fp16
__global__ __launch_bounds__(256)
void conv_kernel(const float* __restrict__ in, __half* __restrict__ o, int n)
{
    int i = (blockIdx.x * 256 + threadIdx.x) * 4;
    if (i >= n) return;
    float4 v = *(const float4*)(in + i);
    *(__half2*)(o + i)     = __halves2half2(__float2half(v.x), __float2half(v.y));
    *(__half2*)(o + i + 2) = __halves2half2(__float2half(v.z), __float2half(v.w));
}

// transpose + convert: W fp32 [Kdim, Ndim] -> W^T fp16 [Ndim, Kdim]
__global__ __launch_bounds__(256)
void convT_kernel(const float* __restrict__ W, __half* __restrict__ WT,
                  int Kdim, int Ndim)
{
    __shared__ float tile[32][33];
    const int k0 = blockIdx.x * 32, n0 = blockIdx.y * 32;
    const int tx = threadIdx.x, ty = threadIdx.y;   // 32 x 8
    #pragma unroll
    for (int i = 0; i < 32; i += 8)
        tile[ty + i][tx] = W[(size_t)(k0 + ty + i) * Ndim + n0 + tx];
    __syncthreads();
    #pragma unroll
    for (int i = 0; i < 32; i += 8) {
        WT[(size_t)(n0 + ty + i) * Kdim + k0 + tx] = __float2half(tile[tx][ty + i]);
    }
}

// ---------------------------------------------------------------------------
// fp16 single-A HMMA GEMM mainloop: C = A * B^T (fp32 accum).
// CTA 128x128, 4 warps 2(M) x 2(N), warp tile 64x64, BK=64,
// 2-stage cp.async pipeline. Stage: A 16K | B 16K = 32KB.
// NOTE: GEMM_SMEM must also cover the V-transpose scratch (128 x 130 fp32
// = 66,560 B) used by the QKV epilogue — this was the round-12 OOB bug.
// ---------------------------------------------------------------------------
#define MAT_BYTES   16384
#define STAGE_BYTES (2 * MAT_BYTES)
#define GEMM_SMEM   69632          // 68KB >= max(2*STAGE_BYTES, 128*130*4)
#define NSTAGE      (KD / 64)

__device__ __forceinline__ void gemm_mainloop(
    const __half* __restrict__ A, const __half* __restrict__ Bh,
    int m0, int n0, uint32_t smem, float (&acc)[4][8][4])
{
    const int tid    = threadIdx.x;      // 0..127
    const int lane   = tid & 31;
    const int warp   = tid >> 5;         // 0..3
    const int warp_m = warp & 1;
    const int warp_n = warp >> 1;        // 0..1

    auto load_stage = [&](int kofs, uint32_t stage_u32) {
        #pragma unroll
        for (int t = 0; t < 16; t++) {
            const int mi  = t >> 3;                   // 0=A, 1=B
            const int rem = ((t & 7) << 7) + tid;     // 0..1023
            const int row = rem >> 3;
            const int ch  = tid & 7;
            const __half* g = (mi == 0 ? A : Bh)
                + (size_t)((mi == 0 ? m0 : n0) + row) * KD + kofs + ch * 8;
            uint32_t s = stage_u32 + mi * MAT_BYTES + row * 128
                       + ((ch ^ (row & 7)) << 4);
            cp16(s, g);
        }
    };

    #pragma unroll
    for (int i = 0; i < 4; i++)
        #pragma unroll
        for (int j = 0; j < 8; j++)
            #pragma unroll
            for (int k = 0; k < 4; k++) acc[i][j][k] = 0.f;

    load_stage(0, smem);
    cp_commit();
    load_stage(64, smem + STAGE_BYTES);
    cp_commit();
    cp_wait1();
    __syncthreads();

    const int arow = warp_m * 64 + (lane & 15);
    const int ah_  = lane >> 4;
    const int brow = warp_n * 64 + ((lane >> 4) << 3) + (lane & 7);
    const int bkh  = (lane >> 3) & 1;

    for (int ks = 0; ks < NSTAGE; ks++) {
        const uint32_t sb = smem + (ks & 1) * STAGE_BYTES;

        #pragma unroll
        for (int kk = 0; kk < 4; kk++) {
            uint32_t ahf[4][4], bhf[8][2];
            #pragma unroll
            for (int mt = 0; mt < 4; mt++) {
                const int r = arow + mt * 16;
                const uint32_t off = r * 128 + ((((kk << 1) | ah_) ^ (r & 7)) << 4);
                LDSM4(ahf[mt], sb + off);
            }
            #pragma unroll
            for (int np = 0; np < 4; np++) {
                const int r = brow + np * 16;
                const uint32_t off = r * 128 + ((((kk << 1) | bkh) ^ (r & 7)) << 4);
                uint32_t q[4];
                LDSM4(q, sb + MAT_BYTES + off);
                bhf[np * 2 + 0][0] = q[0];  bhf[np * 2 + 0][1] = q[1];
                bhf[np * 2 + 1][0] = q[2];  bhf[np * 2 + 1][1] = q[3];
            }
            #pragma unroll
            for (int mt = 0; mt < 4; mt++)
                #pragma unroll
                for (int nt = 0; nt < 8; nt++)
                    mma16816(acc[mt][nt], ahf[mt], bhf[nt]);
        }

        __syncthreads();
        if (ks + 2 < NSTAGE)
            load_stage((ks + 2) * 64, sb);
        cp_commit();
        cp_wait1();
        __syncthreads();
    }
}

// QKV GEMM with fused epilogue: Q (scaled QSCALE) / K head-major fp16,
// V transposed through smem.
__global__ __launch_bounds__(128, 2)
void qkv_gemm_tc()
{
    extern __shared__ __align__(128) char smem_raw[];
    const uint32_t smem = smem_u32(smem_raw);
    const int m0 = blockIdx.y * 128;
    const int n0 = blockIdx.x * 128;
    const int sect = n0 >> 10;       // 0=Q, 1=K, 2=V

    float acc[4][8][4];
    gemm_mainloop(g_xh, g_wah, m0, n0, smem, acc);

    const int tid  = threadIdx.x;
    const int lane = tid & 31;
    const int warp = tid >> 5;
    const int warp_m = warp & 1;
    const int warp_n = warp >> 1;
    const int g  = lane >> 2;
    const int tg = lane & 3;
    const int bb = m0 >> 11;
    const int t0 = m0 & 2047;

    if (sect < 2) {
        const float sc = (sect == 0) ? QSCALE : 1.f;
        __half* dst = (sect == 0) ? g_qh : g_kh;
        const int nc = n0 & 1023;
        #pragma unroll
        for (int mt = 0; mt < 4; mt++) {
            #pragma unroll
            for (int nt = 0; nt < 8; nt++) {
                const int c  = nc + warp_n * 64 + nt * 8 + tg * 2;
                const int hh = c >> 6, d = c & 63;
                const int r  = warp_m * 64 + mt * 16 + g;
                const size_t base = ((size_t)(bb * H_ + hh) * T_ + t0 + r) * DH + d;
                *(__half2*)(dst + base) = __halves2half2(
                    __float2half(acc[mt][nt][0] * sc), __float2half(acc[mt][nt][1] * sc));
                *(__half2*)(dst + base + 8 * DH) = __halves2half2(
                    __float2half(acc[mt][nt][2] * sc), __float2half(acc[mt][nt][3] * sc));
            }
        }
    } else {
        // V: transpose 128x128 tile through smem (stride 130: conflict-free)
        cp_wait0();
        __syncthreads();
        float* sf = (float*)smem_raw;
        #pragma unroll
        for (int mt = 0; mt < 4; mt++) {
            #pragma unroll
            for (int nt = 0; nt < 8; nt++) {
                const int r = warp_m * 64 + mt * 16 + g;
                const int c = warp_n * 64 + nt * 8 + tg * 2;
                sf[r * 130 + c]           = acc[mt][nt][0];
                sf[r * 130 + c + 1]       = acc[mt][nt][1];
                sf[(r + 8) * 130 + c]     = acc[mt][nt][2];
                sf[(r + 8) * 130 + c + 1] = acc[mt][nt][3];
            }
        }
        __syncthreads();
        const int dl = tid;            // column within tile (d), 0..127
        const int nv = (n0 - 2048) + dl;
        const int hh = nv >> 6, d = nv & 63;
        const size_t ob = ((size_t)(bb * H_ + hh) * DH + d) * T_ + t0;
        #pragma unroll 4
        for (int i = 0; i < 128; i += 2) {
            const float v0 = sf[i * 130 + dl];
            const float v1 = sf[(i + 1) * 130 + dl];
            *(__half2*)(g_vth + ob + i) =
                __halves2half2(__float2half(v0), __float2half(v1));
        }
    }
}

// proj GEMM: plain fp32 epilogue to d_out
__global__ __launch_bounds__(128, 2)
void proj_gemm_tc(float* __restrict__ out)
{
    extern __shared__ __align__(128) char smem_raw[];
    const uint32_t smem = smem_u32(smem_raw);
    const int m0 = blockIdx.y * 128;
    const int n0 = blockIdx.x * 128;

    float acc[4][8][4];
    gemm_mainloop(g_yh, g_wph, m0, n0, smem, acc);

    const int lane = threadIdx.x & 31;
    const int warp = threadIdx.x >> 5;
    const int warp_m = warp & 1;
    const int warp_n = warp >> 1;
    const int g  = lane >> 2;
    const int tg = lane & 3;
    #pragma unroll
    for (int mt = 0; mt < 4; mt++) {
        #pragma unroll
        for (int nt = 0; nt < 8; nt++) {
            const int row = m0 + warp_m * 64 + mt * 16 + g;
            const int col = n0 + warp_n * 64 + nt * 8 + tg * 2;
            *(float2*)(out + (size_t)row * C_ + col) =
                make_float2(acc[mt][nt][0], acc[mt][nt][1]);
            *(float2*)(out + (size_t)(row + 8) * C_ + col) =
                make_float2(acc[mt][nt][2], acc[mt][nt][3]);
        }
    }
}

// ---------------------------------------------------------------------------
// fp16 HMMA flash attention: CTA = 128 queries x one (b,h), 8 warps.
// Single fp16 everywhere: Q x K, P x V. Softmax in base 2 (log2e in Q).
// smem: Q 16KB + 3 stages x 16KB = 64KB. 2 CTAs/SM.
// ---------------------------------------------------------------------------
#define ATT_STAGE 16384
#define ATT_SMEM  (16384 + 3 * ATT_STAGE)

__global__ __launch_bounds__(256, 2)
void attn_hmma_kernel()
{
    extern __shared__ __align__(128) char smem_raw[];
    const uint32_t smem = smem_u32(smem_raw);
    const uint32_t qsm  = smem;
    const uint32_t st0  = smem + 16384;

    const int tid  = threadIdx.x;
    const int lane = tid & 31;
    const int warp = tid >> 5;                       // 0..7
    const int qt   = (gridDim.x - 1) - blockIdx.x;   // heavy first
    const int bh   = blockIdx.z * H_ + blockIdx.y;
    const size_t qkb = (size_t)bh * T_ * DH;
    const size_t vb  = (size_t)bh * DH * T_;
    const int nkt = 2 * (qt + 1);

    // Q tile load (once; 4 chunks/thread)
    {
        const __half* s0 = g_qh + qkb + (size_t)qt * 128 * DH;
        #pragma unroll
        for (int t = 0; t < 4; t++) {
            const int rem = (t << 8) + tid;          // 0..1023
            const int row = rem >> 3, ch = tid & 7;
            cp16(qsm + row * 128 + ((ch ^ (row & 7)) << 4),
                 s0 + (size_t)row * DH + ch * 8);
        }
    }
    auto load_kv = [&](int kt, uint32_t stage) {
        #pragma unroll
        for (int t = 0; t < 4; t++) {
            const int mat = t >> 1;                  // 0=Kh, 1=Vth
            const int rem = ((t & 1) << 8) + tid;    // 0..511
            const int row = rem >> 3, ch = tid & 7;
            const __half* g = (mat == 0)
                ? g_kh  + qkb + (size_t)(kt * 64 + row) * DH + ch * 8
                : g_vth + vb  + (size_t)row * T_ + kt * 64 + ch * 8;
            cp16(stage + mat * 8192 + row * 128 + ((ch ^ (row & 7)) << 4), g);
        }
    };

    load_kv(0, st0);
    cp_commit();                 // group: Q + kv0
    load_kv(1, st0 + ATT_STAGE);
    cp_commit();                 // group: kv1

    const int g   = lane >> 2;
    const int c2  = (lane & 3) * 2;
    const int q0w = qt * 128 + warp * 16;
    const int bkh = (lane >> 3) & 1;
    const int ah_ = lane >> 4;
    const int brow_base = ((lane >> 4) << 3) + (lane & 7);

    float O[8][4];
    #pragma unroll
    for (int nt = 0; nt < 8; nt++)
        #pragma unroll
        for (int i = 0; i < 4; i++) O[nt][i] = 0.f;
    float mrun0 = -1e30f, mrun1 = -1e30f;
    float lrun0 = 0.f, lrun1 = 0.f;

    for (int kt = 0; kt < nkt; kt++) {
        cp_wait1();
        __syncthreads();

        // prefetch kt+2 into the buffer freed by the barrier
        const uint32_t nb = st0 + ((kt + 2) % 3) * ATT_STAGE;
        if (kt + 2 < nkt) load_kv(kt + 2, nb);
        else              cp16(nb + tid * 16, g_kh + tid * 8);   // real dummy
        cp_commit();

        const uint32_t sb = st0 + (kt % 3) * ATT_STAGE;

        float sacc[8][4];
        #pragma unroll
        for (int nt = 0; nt < 8; nt++)
            #pragma unroll
            for (int i = 0; i < 4; i++) sacc[nt][i] = 0.f;

        // ---- S' = (Q*QSCALE) K^T  (base-2 logits) ----
        #pragma unroll
        for (int kk = 0; kk < 4; kk++) {
            uint32_t qhf[4];
            {
                const int r = warp * 16 + (lane & 15);
                const uint32_t off = r * 128 + ((((kk << 1) | ah_) ^ (r & 7)) << 4);
                LDSM4(qhf, qsm + off);
            }
            uint32_t khf[8][2];
            #pragma unroll
            for (int np = 0; np < 4; np++) {
                const int r = np * 16 + brow_base;
                const uint32_t off = r * 128 + ((((kk << 1) | bkh) ^ (r & 7)) << 4);
                uint32_t q4[4];
                LDSM4(q4, sb + off);
                khf[np * 2 + 0][0] = q4[0];  khf[np * 2 + 0][1] = q4[1];
                khf[np * 2 + 1][0] = q4[2];  khf[np * 2 + 1][1] = q4[3];
            }
            #pragma unroll
            for (int nt = 0; nt < 8; nt++)
                mma16816(sacc[nt], qhf, khf[nt]);
        }

        // ---- causal mask (diagonal tiles only) ----
        if (kt >= 2 * qt) {
            const int kt64 = kt * 64;
            const int qr0 = q0w + g;
            #pragma unroll
            for (int nt = 0; nt < 8; nt++) {
                const int kc = kt64 + nt * 8 + c2;
                if (kc > qr0)         sacc[nt][0] = -1e30f;
                if (kc + 1 > qr0)     sacc[nt][1] = -1e30f;
                if (kc > qr0 + 8)     sacc[nt][2] = -1e30f;
                if (kc + 1 > qr0 + 8) sacc[nt][3] = -1e30f;
            }
        }

        // ---- online softmax (base 2) ----
        {
            float h0 = -1e30f, h1 = -1e30f;
            #pragma unroll
            for (int nt = 0; nt < 8; nt++) {
                h0 = fmaxf(h0, fmaxf(sacc[nt][0], sacc[nt][1]));
                h1 = fmaxf(h1, fmaxf(sacc[nt][2], sacc[nt][3]));
            }
            h0 = fmaxf(h0, __shfl_xor_sync(0xffffffffu, h0, 1));
            h0 = fmaxf(h0, __shfl_xor_sync(0xffffffffu, h0, 2));
            h1 = fmaxf(h1, __shfl_xor_sync(0xffffffffu, h1, 1));
            h1 = fmaxf(h1, __shfl_xor_sync(0xffffffffu, h1, 2));
            const float m0 = fmaxf(mrun0, h0);
            const float m1 = fmaxf(mrun1, h1);
            const float a0 = ex2(mrun0 - m0);
            const float a1 = ex2(mrun1 - m1);
            mrun0 = m0;  mrun1 = m1;

            float s0 = 0.f, s1 = 0.f;
            #pragma unroll
            for (int nt = 0; nt < 8; nt++) {
                float p0 = ex2(sacc[nt][0] - m0);
                float p1 = ex2(sacc[nt][1] - m0);
                float p2 = ex2(sacc[nt][2] - m1);
                float p3 = ex2(sacc[nt][3] - m1);
                sacc[nt][0] = p0;  sacc[nt][1] = p1;
                sacc[nt][2] = p2;  sacc[nt][3] = p3;
                s0 += p0 + p1;
                s1 += p2 + p3;
            }
            s0 += __shfl_xor_sync(0xffffffffu, s0, 1);
            s0 += __shfl_xor_sync(0xffffffffu, s0, 2);
            s1 += __shfl_xor_sync(0xffffffffu, s1, 1);
            s1 += __shfl_xor_sync(0xffffffffu, s1, 2);
            lrun0 = lrun0 * a0 + s0;
            lrun1 = lrun1 * a1 + s1;

            #pragma unroll
            for (int nt = 0; nt < 8; nt++) {
                O[nt][0] *= a0;
                O[nt][1] *= a0;
                O[nt][2] *= a1;
                O[nt][3] *= a1;
            }
        }

        // ---- O += P V (P single fp16) ----
        #pragma unroll
        for (int kc = 0; kc < 4; kc++) {
            uint32_t ph[4];
            #pragma unroll
            for (int half = 0; half < 2; half++) {
                const int nt = 2 * kc + half;
                ph[half * 2 + 0] = pack_f16x2(sacc[nt][0], sacc[nt][1]);
                ph[half * 2 + 1] = pack_f16x2(sacc[nt][2], sacc[nt][3]);
            }
            uint32_t vh[8][2];
            #pragma unroll
            for (int np = 0; np < 4; np++) {
                const int r = np * 16 + brow_base;
                const uint32_t off = r * 128 + ((((kc << 1) | bkh) ^ (r & 7)) << 4);
                uint32_t q4[4];
                LDSM4(q4, sb + 8192 + off);
                vh[np * 2 + 0][0] = q4[0];  vh[np * 2 + 0][1] = q4[1];
                vh[np * 2 + 1][0] = q4[2];  vh[np * 2 + 1][1] = q4[3];
            }
            #pragma unroll
            for (int nt = 0; nt < 8; nt++)
                mma16816(O[nt], ph, vh[nt]);
        }
    }

    // ---- epilogue: y = O / l, written as fp16 for the proj GEMM ----
    const int hcol = blockIdx.y * 64;
    const float inv0 = 1.f / lrun0;
    const float inv1 = 1.f / lrun1;
    const int r0 = blockIdx.z * T_ + q0w + g;
    #pragma unroll
    for (int nt = 0; nt < 8; nt++) {
        const size_t o0 = (size_t)r0 * C_ + hcol + nt * 8 + c2;
        const size_t o1 = o0 + (size_t)8 * C_;
        *(__half2*)(g_yh + o0) = __halves2half2(
            __float2half(O[nt][0] * inv0), __float2half(O[nt][1] * inv0));
        *(__half2*)(g_yh + o1) = __halves2half2(
            __float2half(O[nt][2] * inv1), __float2half(O[nt][3] * inv1));
    }
}

// ---------------------------------------------------------------------------
extern "C" void kernel_launch(void* const* d_in, const int* in_sizes, int n_in,
                              void* d_out, int out_size)
{
    const float* x      = (const float*)d_in[0];
    const float* w_attn = (const float*)d_in[1];
    const float* w_proj = (const float*)d_in[2];
    float* out = (float*)d_out;

    static bool attr_done = false;
    if (!attr_done) {
        cudaFuncSetAttribute(qkv_gemm_tc,  cudaFuncAttributeMaxDynamicSharedMemorySize, GEMM_SMEM);
        cudaFuncSetAttribute(proj_gemm_tc, cudaFuncAttributeMaxDynamicSharedMemorySize, GEMM_SMEM);
        cudaFuncSetAttribute(attn_hmma_kernel, cudaFuncAttributeMaxDynamicSharedMemorySize, ATT_SMEM);
        attr_done = true;
    }

    __half *xh, *wah, *wph;
    cudaGetSymbolAddress((void**)&xh,  g_xh);
    cudaGetSymbolAddress((void**)&wah, g_wah);
    cudaGetSymbolAddress((void**)&wph, g_wph);

    // 1) convert x -> fp16
    conv_kernel<<<(M_ * KD) / 1024, 256>>>(x, xh, M_ * KD);
    // 2) transpose+convert weights to fp16
    {
        dim3 grid(KD / 32, (3 * C_) / 32);
        convT_kernel<<<grid, dim3(32, 8)>>>(w_attn, wah, KD, 3 * C_);
    }
    {
        dim3 grid(KD / 32, C_ / 32);
        convT_kernel<<<grid, dim3(32, 8)>>>(w_proj, wph, KD, C_);
    }
    // 3) QKV GEMM (single-A fp16) with fused head-major epilogue
    {
        dim3 grid((3 * C_) / 128, M_ / 128);
        qkv_gemm_tc<<<grid, 128, GEMM_SMEM>>>();
    }
    // 4) HMMA flash attention (all single fp16, base-2 softmax) -> g_yh
    {
        dim3 grid(T_ / 128, H_, B_);
        attn_hmma_kernel<<<grid, 256, ATT_SMEM>>>();
    }
    // 5) proj GEMM (single-A fp16) -> out
    {
        dim3 grid(C_ / 128, M_ / 128);
        proj_gemm_tc<<<grid, 128, GEMM_SMEM>>>(out);
    }
}